// round 11
// baseline (speedup 1.0000x reference)
#include <cuda_runtime.h>
#include <math.h>

// Problem dims
#define B   128
#define T   64
#define Xd  64
#define H   512
#define D   512
#define Z   64
#define KF  2
#define G   1536          // 3*H
#define BT  8192          // B*T
#define S   524288        // B*T*64
#define NBLK 128
#define SCAN_THREADS 512
#define SCAN_WARPS 16
// ws[512*24] + red[16*24*64] + sbh[32]
#define SCAN_SMEM ((512*24 + 16*24*64 + 32) * 4)

typedef unsigned long long ull;

// ---------------- scratch ----------------
__device__ float  g_xT[BT * Xd];           // x rearranged to [t*B+b][X]
__device__ float  g_gi[T * G * B];         // gi TRANSPOSED: [t][col][b]
__device__ float  g_h[(T + 1) * H * B];    // h TRANSPOSED: [t][k][b], slab 0 = zeros
__device__ float  g_phi[BT * D];
__device__ float  g_head[BT * 128];
__device__ float  g_z[BT * Z];
__device__ float  g_WheadZ[128 * 512];
__device__ float  g_bheadZ[128];
__device__ float  g_WheadX[128 * 512];
__device__ float  g_bheadX[128];
__device__ double g_pz[2048];              // kld_z partials (flow blocks)
__device__ double g_pn[2048];              // nll partials (dec_out blocks)
__device__ double g_px[2048];              // kld_x partials (dec_out blocks)
__device__ unsigned g_bar_count2[2] = {0, 0};
__device__ unsigned g_bar_gen2[2]   = {0, 0};

// ---------------- helpers ----------------
__device__ __forceinline__ float sigmoidf_(float v) { return 1.0f / (1.0f + expf(-v)); }
__device__ __forceinline__ float softplusf_(float v) { return (v > 20.0f) ? v : log1pf(expf(v)); }
__device__ __forceinline__ float fsigmoid_(float v) { return 1.0f / (1.0f + __expf(-v)); }
__device__ __forceinline__ float ftanh_(float v) { return 1.0f - 2.0f / (__expf(2.0f * v) + 1.0f); }

__device__ __forceinline__ void fma2(ull &a, ull x, ull y) {
    asm("fma.rn.f32x2 %0, %1, %2, %0;" : "+l"(a) : "l"(x), "l"(y));
}
__device__ __forceinline__ ull pack2(float lo, float hi) {
    ull r;
    asm("mov.b64 %0, {%1, %2};" : "=l"(r) : "f"(lo), "f"(hi));
    return r;
}
__device__ __forceinline__ float2 unpack2(ull v) {
    float2 r;
    asm("mov.b64 {%0, %1}, %2;" : "=f"(r.x), "=f"(r.y) : "l"(v));
    return r;
}

// monotonic-counter barrier over the 64 blocks of one b-half
__device__ __forceinline__ void half_barrier(int g) {
    __threadfence();
    __syncthreads();
    if (threadIdx.x == 0) {
        volatile unsigned* vgen = &g_bar_gen2[g];
        unsigned gen = *vgen;
        unsigned prev = atomicAdd(&g_bar_count2[g], 1u);
        if ((prev & 63u) == 63u) {
            __threadfence();
            *vgen = gen + 1;
        } else {
            while (*vgen == gen) { }
            __threadfence();
        }
    }
    __syncthreads();
}

// ---------------- fused prep: transpose x, zero h0, pack both head weights ----------------
__global__ void k_prep(const float* __restrict__ x,
                       const float* __restrict__ Wzm, const float* __restrict__ bzm,
                       const float* __restrict__ Wzs, const float* __restrict__ bzs,
                       const float* __restrict__ Wxm, const float* __restrict__ bxm,
                       const float* __restrict__ Wxs, const float* __restrict__ bxs,
                       float* __restrict__ xT, float* __restrict__ h0,
                       float* __restrict__ WhZ, float* __restrict__ bhZ,
                       float* __restrict__ WhX, float* __restrict__ bhX) {
    int i = blockIdx.x * blockDim.x + threadIdx.x;
    if (i < 524288) {
        int b = i >> 12;
        int r = i & 4095;
        int t = r >> 6;
        int xi = r & 63;
        xT[((t << 7) + b) * Xd + xi] = x[i];
    } else if (i < 589824) {
        h0[i - 524288] = 0.0f;
    } else if (i < 622592) {
        int q = i - 589824; WhZ[q] = Wzm[q];
    } else if (i < 655360) {
        int q = i - 622592; WhZ[32768 + q] = Wzs[q];
    } else if (i < 688128) {
        int q = i - 655360; WhX[q] = Wxm[q];
    } else if (i < 720896) {
        int q = i - 688128; WhX[32768 + q] = Wxs[q];
    } else if (i < 721152) {
        int q = i - 720896;  // 0..255
        if (q < 64)        bhZ[q] = bzm[q];
        else if (q < 128)  bhZ[q] = bzs[q - 64];
        else if (q < 192)  bhX[q - 128] = bxm[q - 128];
        else               bhX[q - 128] = bxs[q - 192];
    }
}

// ---------------- tiled GEMM 128x128, 256 threads, 8x8 per thread, pipelined ----------------
// Conflict-free A reads (m = ty + 16*mi scalar LDS) + forced 2 blocks/SM.
__global__ void __launch_bounds__(256, 2)
k_gemm(const float* __restrict__ A, int lda,
       const float* __restrict__ W, int ldw,
       const float* __restrict__ bias,
       float* __restrict__ C, int ldc,
       int K, int act, int cmode) {
    __shared__ float As[16 * 132];
    __shared__ float Ws[16 * 132];
    const int m0 = blockIdx.x * 128;
    const int n0 = blockIdx.y * 128;
    const int tx = threadIdx.x >> 4;
    const int ty = threadIdx.x & 15;
    const int lm = threadIdx.x >> 1;
    const int lq = (threadIdx.x & 1) * 8;

    const float* Aptr = A + (size_t)(m0 + lm) * lda + lq;
    const float* Wptr = W + (size_t)(n0 + lm) * ldw + lq;

    ull acc[8][4];
    #pragma unroll
    for (int i = 0; i < 8; i++)
        #pragma unroll
        for (int j = 0; j < 4; j++) acc[i][j] = 0ull;

    float4 a0 = *reinterpret_cast<const float4*>(Aptr);
    float4 a1 = *reinterpret_cast<const float4*>(Aptr + 4);
    float4 w0 = *reinterpret_cast<const float4*>(Wptr);
    float4 w1 = *reinterpret_cast<const float4*>(Wptr + 4);

    for (int k0 = 0; k0 < K; k0 += 16) {
        As[(lq + 0) * 132 + lm] = a0.x; As[(lq + 1) * 132 + lm] = a0.y;
        As[(lq + 2) * 132 + lm] = a0.z; As[(lq + 3) * 132 + lm] = a0.w;
        As[(lq + 4) * 132 + lm] = a1.x; As[(lq + 5) * 132 + lm] = a1.y;
        As[(lq + 6) * 132 + lm] = a1.z; As[(lq + 7) * 132 + lm] = a1.w;
        Ws[(lq + 0) * 132 + lm] = w0.x; Ws[(lq + 1) * 132 + lm] = w0.y;
        Ws[(lq + 2) * 132 + lm] = w0.z; Ws[(lq + 3) * 132 + lm] = w0.w;
        Ws[(lq + 4) * 132 + lm] = w1.x; Ws[(lq + 5) * 132 + lm] = w1.y;
        Ws[(lq + 6) * 132 + lm] = w1.z; Ws[(lq + 7) * 132 + lm] = w1.w;
        __syncthreads();

        int kn = (k0 + 16 < K) ? (k0 + 16) : k0;
        a0 = *reinterpret_cast<const float4*>(Aptr + kn);
        a1 = *reinterpret_cast<const float4*>(Aptr + kn + 4);
        w0 = *reinterpret_cast<const float4*>(Wptr + kn);
        w1 = *reinterpret_cast<const float4*>(Wptr + kn + 4);

        #pragma unroll
        for (int k = 0; k < 16; k++) {
            float am[8];
            #pragma unroll
            for (int mi = 0; mi < 8; mi++) am[mi] = As[k * 132 + ty + 16 * mi];
            ulonglong2 bn0 = *reinterpret_cast<const ulonglong2*>(Ws + k * 132 + tx * 8);
            ulonglong2 bn1 = *reinterpret_cast<const ulonglong2*>(Ws + k * 132 + tx * 8 + 4);
            ull bp[4] = {bn0.x, bn0.y, bn1.x, bn1.y};
            #pragma unroll
            for (int mi = 0; mi < 8; mi++) {
                ull a2 = pack2(am[mi], am[mi]);
                #pragma unroll
                for (int np = 0; np < 4; np++) fma2(acc[mi][np], a2, bp[np]);
            }
        }
        __syncthreads();
    }

    float cv[8][8];
    #pragma unroll
    for (int mi = 0; mi < 8; mi++) {
        #pragma unroll
        for (int np = 0; np < 4; np++) {
            float2 p = unpack2(acc[mi][np]);
            float v0 = p.x + bias[n0 + tx * 8 + 2 * np];
            float v1 = p.y + bias[n0 + tx * 8 + 2 * np + 1];
            if (act == 1) { v0 = fmaxf(v0, 0.0f); v1 = fmaxf(v1, 0.0f); }
            cv[mi][2 * np] = v0; cv[mi][2 * np + 1] = v1;
        }
    }
    if (cmode == 0) {
        #pragma unroll
        for (int mi = 0; mi < 8; mi++) {
            int m = m0 + ty + 16 * mi;
            float4 s0 = make_float4(cv[mi][0], cv[mi][1], cv[mi][2], cv[mi][3]);
            float4 s1 = make_float4(cv[mi][4], cv[mi][5], cv[mi][6], cv[mi][7]);
            *reinterpret_cast<float4*>(C + (size_t)m * ldc + n0 + tx * 8)     = s0;
            *reinterpret_cast<float4*>(C + (size_t)m * ldc + n0 + tx * 8 + 4) = s1;
        }
    } else {
        const int t = blockIdx.x;          // m-tile == one full B
        #pragma unroll
        for (int j = 0; j < 8; j++) {
            int n = n0 + tx * 8 + j;
            size_t base = ((size_t)t * ldc + n) * B;
            #pragma unroll
            for (int mi = 0; mi < 8; mi++)
                C[base + ty + 16 * mi] = cv[mi][j];
        }
    }
}

// ---------------- GEMM variant: A from transposed h [(t+1)][k][b], pipelined ----------------
__global__ void __launch_bounds__(256, 2)
k_gemm_ht(const float* __restrict__ hT,
          const float* __restrict__ W, int ldw,
          const float* __restrict__ bias,
          float* __restrict__ C, int ldc,
          int K, int act) {
    __shared__ float As[16 * 132];
    __shared__ float Ws[16 * 132];
    const int m0 = blockIdx.x * 128;
    const int n0 = blockIdx.y * 128;
    const size_t slab = (size_t)(blockIdx.x + 1) * (H * B);
    const int tx = threadIdx.x >> 4;
    const int ty = threadIdx.x & 15;
    const int lm = threadIdx.x >> 1;
    const int lq = (threadIdx.x & 1) * 8;
    const int lk = threadIdx.x >> 4;
    const int lb = (threadIdx.x & 15) * 8;

    const float* Hptr = hT + slab + (size_t)lk * B + lb;
    const float* Wptr = W + (size_t)(n0 + lm) * ldw + lq;

    ull acc[8][4];
    #pragma unroll
    for (int i = 0; i < 8; i++)
        #pragma unroll
        for (int j = 0; j < 4; j++) acc[i][j] = 0ull;

    float4 h0 = *reinterpret_cast<const float4*>(Hptr);
    float4 h1 = *reinterpret_cast<const float4*>(Hptr + 4);
    float4 w0 = *reinterpret_cast<const float4*>(Wptr);
    float4 w1 = *reinterpret_cast<const float4*>(Wptr + 4);

    for (int k0 = 0; k0 < K; k0 += 16) {
        *reinterpret_cast<float4*>(As + lk * 132 + lb)     = h0;
        *reinterpret_cast<float4*>(As + lk * 132 + lb + 4) = h1;
        Ws[(lq + 0) * 132 + lm] = w0.x; Ws[(lq + 1) * 132 + lm] = w0.y;
        Ws[(lq + 2) * 132 + lm] = w0.z; Ws[(lq + 3) * 132 + lm] = w0.w;
        Ws[(lq + 4) * 132 + lm] = w1.x; Ws[(lq + 5) * 132 + lm] = w1.y;
        Ws[(lq + 6) * 132 + lm] = w1.z; Ws[(lq + 7) * 132 + lm] = w1.w;
        __syncthreads();

        int kn = (k0 + 16 < K) ? (k0 + 16) : k0;
        h0 = *reinterpret_cast<const float4*>(Hptr + (size_t)kn * B);
        h1 = *reinterpret_cast<const float4*>(Hptr + (size_t)kn * B + 4);
        w0 = *reinterpret_cast<const float4*>(Wptr + kn);
        w1 = *reinterpret_cast<const float4*>(Wptr + kn + 4);

        #pragma unroll
        for (int k = 0; k < 16; k++) {
            float am[8];
            #pragma unroll
            for (int mi = 0; mi < 8; mi++) am[mi] = As[k * 132 + ty + 16 * mi];
            ulonglong2 bn0 = *reinterpret_cast<const ulonglong2*>(Ws + k * 132 + tx * 8);
            ulonglong2 bn1 = *reinterpret_cast<const ulonglong2*>(Ws + k * 132 + tx * 8 + 4);
            ull bp[4] = {bn0.x, bn0.y, bn1.x, bn1.y};
            #pragma unroll
            for (int mi = 0; mi < 8; mi++) {
                ull a2 = pack2(am[mi], am[mi]);
                #pragma unroll
                for (int np = 0; np < 4; np++) fma2(acc[mi][np], a2, bp[np]);
            }
        }
        __syncthreads();
    }
    #pragma unroll
    for (int mi = 0; mi < 8; mi++) {
        int m = m0 + ty + 16 * mi;
        float cv[8];
        #pragma unroll
        for (int np = 0; np < 4; np++) {
            float2 p = unpack2(acc[mi][np]);
            float v0 = p.x + bias[n0 + tx * 8 + 2 * np];
            float v1 = p.y + bias[n0 + tx * 8 + 2 * np + 1];
            if (act == 1) { v0 = fmaxf(v0, 0.0f); v1 = fmaxf(v1, 0.0f); }
            cv[2 * np] = v0; cv[2 * np + 1] = v1;
        }
        float4 s0 = make_float4(cv[0], cv[1], cv[2], cv[3]);
        float4 s1 = make_float4(cv[4], cv[5], cv[6], cv[7]);
        *reinterpret_cast<float4*>(C + (size_t)m * ldc + n0 + tx * 8)     = s0;
        *reinterpret_cast<float4*>(C + (size_t)m * ldc + n0 + tx * 8 + 4) = s1;
    }
}

// ---------------- persistent GRU scan, b-split v2 ----------------
// 128 blocks = 2 b-halves x 64 col-groups. Block: 24 cols (8j x 3g), 64-b half.
// 16 warps = 16 k-slices of 32 (same as before). Per k per thread:
// 1 LDG.64 (h pair) + 6 broadcast LDS.128 (w) + 24 FFMA2 — same issue profile
// as the 128-b version, but each block reads only HALF the h slab.
extern __shared__ float smem_dyn[];

__global__ void __launch_bounds__(SCAN_THREADS, 1)
k_gru_scan(const float* __restrict__ giT,  // [T][G][B]
           const float* __restrict__ Wh,   // [G, H]
           const float* __restrict__ bh,   // [G]
           float* __restrict__ hT)         // [(T+1), H, B]
{
    float* ws  = smem_dyn;                 // [512][24] : ws[k*24 + c], c = g*8+jj
    float* red = ws + 512 * 24;            // [16][24][64]
    float* sbh = red + 16 * 24 * 64;       // [24]
    const int tid  = threadIdx.x;
    const int warp = tid >> 5;
    const int lane = tid & 31;
    const int bhalf = blockIdx.x >> 6;     // 0/1
    const int cg    = blockIdx.x & 63;
    const int j0    = cg * 8;
    const int b0    = bhalf * 64;

    for (int i = tid; i < 24 * 512; i += SCAN_THREADS) {
        int c = i >> 9, k = i & 511;
        ws[k * 24 + c] = Wh[((size_t)((c >> 3) * H + j0 + (c & 7))) * H + k];
    }
    if (tid < 24) sbh[tid] = bh[(tid >> 3) * H + j0 + (tid & 7)];
    __syncthreads();

    const int k0 = warp * 32;
    const int bb = b0 + lane * 2;
    const int gj = tid >> 6;        // 0..7 gate-phase j
    const int gb = tid & 63;        // 0..63 b within half
    const float bias_r = sbh[gj];
    const float bias_z = sbh[8 + gj];
    const float bias_n = sbh[16 + gj];

    for (int t = 0; t < T; t++) {
        const float* hprev = hT + (size_t)t * (H * B);

        // prefetch gate-phase operands (coalesced; completes under the k-loop)
        size_t gib = ((size_t)t * G + j0 + gj) * B + b0 + gb;
        float ir  = giT[gib];
        float iz  = giT[gib + (size_t)H * B];
        float inn = giT[gib + (size_t)2 * H * B];
        float hp  = hprev[(size_t)(j0 + gj) * B + b0 + gb];

        ull acc[2][12];
        #pragma unroll
        for (int i = 0; i < 2; i++)
            #pragma unroll
            for (int cp = 0; cp < 12; cp++) acc[i][cp] = 0ull;

        #pragma unroll 4
        for (int kk = 0; kk < 32; kk++) {
            int k = k0 + kk;
            float2 hv = *reinterpret_cast<const float2*>(hprev + (size_t)k * B + bb);
            ull h20 = pack2(hv.x, hv.x);
            ull h21 = pack2(hv.y, hv.y);
            const float* wrow = ws + k * 24;
            ulonglong2 q0 = *reinterpret_cast<const ulonglong2*>(wrow);
            ulonglong2 q1 = *reinterpret_cast<const ulonglong2*>(wrow + 4);
            ulonglong2 q2 = *reinterpret_cast<const ulonglong2*>(wrow + 8);
            ulonglong2 q3 = *reinterpret_cast<const ulonglong2*>(wrow + 12);
            ulonglong2 q4 = *reinterpret_cast<const ulonglong2*>(wrow + 16);
            ulonglong2 q5 = *reinterpret_cast<const ulonglong2*>(wrow + 20);
            ull wp[12] = {q0.x, q0.y, q1.x, q1.y, q2.x, q2.y,
                          q3.x, q3.y, q4.x, q4.y, q5.x, q5.y};
            #pragma unroll
            for (int cp = 0; cp < 12; cp++) {
                fma2(acc[0][cp], h20, wp[cp]);
                fma2(acc[1][cp], h21, wp[cp]);
            }
        }

        // red[(warp*24 + c)*64 + b] ; STS.64 over b-pairs, conflict-free
        #pragma unroll
        for (int cp = 0; cp < 12; cp++) {
            float2 v0 = unpack2(acc[0][cp]);   // cols 2cp,2cp+1 at b = lane*2
            float2 v1 = unpack2(acc[1][cp]);   // cols 2cp,2cp+1 at b = lane*2+1
            *reinterpret_cast<float2*>(red + ((size_t)(warp * 24 + 2 * cp)) * 64 + lane * 2)
                = make_float2(v0.x, v1.x);
            *reinterpret_cast<float2*>(red + ((size_t)(warp * 24 + 2 * cp + 1)) * 64 + lane * 2)
                = make_float2(v0.y, v1.y);
        }
        __syncthreads();

        // gate phase: 512 outputs (8 j x 64 b), one per thread
        {
            float gr = 0.f, gz = 0.f, gn = 0.f;
            #pragma unroll
            for (int w = 0; w < SCAN_WARPS; w++) {
                gr += red[(w * 24 + gj) * 64 + gb];
                gz += red[(w * 24 + 8 + gj) * 64 + gb];
                gn += red[(w * 24 + 16 + gj) * 64 + gb];
            }
            float r = fsigmoid_(ir + gr + bias_r);
            float u = fsigmoid_(iz + gz + bias_z);
            float n = ftanh_(inn + r * (gn + bias_n));
            hT[((size_t)(t + 1) * H + j0 + gj) * B + b0 + gb] = (1.0f - u) * n + u * hp;
        }

        half_barrier(bhalf);
    }
}

// ---------------- encoder output: zm, zs, z, planar flow + kld_z partials ----------------
__global__ void k_flow_enc(const float* __restrict__ head,
                           const float* __restrict__ eps_enc,
                           const float* __restrict__ w_flow,
                           const float* __restrict__ b_flow,
                           const float* __restrict__ u_flow,
                           float* __restrict__ out,
                           float* __restrict__ z_all,
                           double* __restrict__ pz) {
    __shared__ float red[4][64];
    __shared__ double dred[256];
    int rl = threadIdx.x >> 6;
    int j = threadIdx.x & 63;
    int row = blockIdx.x * 4 + rl;       // t*B + b
    int t = row >> 7;
    int b = row & 127;

    float zm = sigmoidf_(head[row * 128 + j]);
    float zs = softplusf_(head[row * 128 + 64 + j]);
    float eps = eps_enc[b * (T * Z) + t * Z + j];
    float z = eps * zs + zm;

    #pragma unroll
    for (int k = 0; k < KF; k++) {
        red[rl][j] = z * w_flow[(t * KF + k) * Z + j];
        __syncthreads();
        #pragma unroll
        for (int s = 32; s > 0; s >>= 1) {
            if (j < s) red[rl][j] += red[rl][j + s];
            __syncthreads();
        }
        float sv = red[rl][0] + b_flow[t * KF + k];
        __syncthreads();
        z += u_flow[(t * KF + k) * Z + j] * tanhf(sv);
    }

    int o = (b * T + t) * Z + j;
    out[2 + o]         = z;
    out[2 + S + o]     = zm;
    out[2 + 2 * S + o] = zs;
    z_all[row * Z + j] = z;

    // kld_z partial: 1 + zs - zm^2 - exp(zs) (float exp, double accumulate)
    float ez = expf(zs);
    dred[threadIdx.x] = 1.0 + (double)zs - (double)zm * (double)zm - (double)ez;
    __syncthreads();
    for (int s = 128; s > 0; s >>= 1) {
        if (threadIdx.x < s) dred[threadIdx.x] += dred[threadIdx.x + s];
        __syncthreads();
    }
    if (threadIdx.x == 0) pz[blockIdx.x] = dred[0];
}

// ---------------- decoder output + nll/kld_x partials ----------------
__global__ void k_dec_out(const float* __restrict__ head,
                          const float* __restrict__ eps_dec,
                          const float* __restrict__ x,
                          float* __restrict__ out,
                          double* __restrict__ pn,
                          double* __restrict__ px) {
    __shared__ double sn[256];
    __shared__ double sk[256];
    int i = blockIdx.x * blockDim.x + threadIdx.x;
    int row = i >> 6;
    int j = i & 63;
    int t = row >> 7;
    int b = row & 127;
    float xm = sigmoidf_(head[row * 128 + j]);
    float xs = softplusf_(head[row * 128 + 64 + j]);
    int src = b * (T * Xd) + t * Xd + j;
    float eps = eps_dec[src];
    float xo = eps * xs + xm;
    int o = (b * T + t) * Xd + j;
    out[2 + 3 * S + o] = xo;
    out[2 + 4 * S + o] = xm;
    out[2 + 5 * S + o] = xs;

    float xv = x[src];
    float dq = (xv - xm) * expf(-0.5f * xs);
    float ex = expf(xs);
    sn[threadIdx.x] = (double)xs + (double)dq * (double)dq;
    sk[threadIdx.x] = 1.0 + (double)xs - (double)xm * (double)xm - (double)ex;
    __syncthreads();
    for (int s = 128; s > 0; s >>= 1) {
        if (threadIdx.x < s) {
            sn[threadIdx.x] += sn[threadIdx.x + s];
            sk[threadIdx.x] += sk[threadIdx.x + s];
        }
        __syncthreads();
    }
    if (threadIdx.x == 0) {
        pn[blockIdx.x] = sn[0];
        px[blockIdx.x] = sk[0];
    }
}

// ---------------- final deterministic reduction ----------------
__global__ void k_reduce_final(const double* __restrict__ pz,
                               const double* __restrict__ pn,
                               const double* __restrict__ px,
                               float* __restrict__ out) {
    __shared__ double sn[256];
    __shared__ double sk[256];
    double an = 0.0, ak = 0.0;
    for (int i = threadIdx.x; i < 2048; i += 256) {
        an += pn[i];
        ak += pz[i] + px[i];
    }
    sn[threadIdx.x] = an;
    sk[threadIdx.x] = ak;
    __syncthreads();
    for (int s = 128; s > 0; s >>= 1) {
        if (threadIdx.x < s) {
            sn[threadIdx.x] += sn[threadIdx.x + s];
            sk[threadIdx.x] += sk[threadIdx.x + s];
        }
        __syncthreads();
    }
    if (threadIdx.x == 0) {
        out[0] = (float)(0.5 * sn[0]);
        out[1] = (float)(-0.5 * sk[0]);
    }
}

// ---------------- launch ----------------
extern "C" void kernel_launch(void* const* d_in, const int* in_sizes, int n_in,
                              void* d_out, int out_size) {
    const float* x        = (const float*)d_in[0];
    const float* eps_enc  = (const float*)d_in[1];
    const float* eps_dec  = (const float*)d_in[2];
    const float* Wi_enc   = (const float*)d_in[3];
    const float* Wh_enc   = (const float*)d_in[4];
    const float* bi_enc   = (const float*)d_in[5];
    const float* bh_enc   = (const float*)d_in[6];
    const float* Wphi_enc = (const float*)d_in[7];
    const float* bphi_enc = (const float*)d_in[8];
    const float* W_zmean  = (const float*)d_in[9];
    const float* b_zmean  = (const float*)d_in[10];
    const float* W_zstd   = (const float*)d_in[11];
    const float* b_zstd   = (const float*)d_in[12];
    const float* w_flow   = (const float*)d_in[13];
    const float* b_flow   = (const float*)d_in[14];
    const float* u_flow   = (const float*)d_in[15];
    const float* Wi_dec   = (const float*)d_in[16];
    const float* Wh_dec   = (const float*)d_in[17];
    const float* bi_dec   = (const float*)d_in[18];
    const float* bh_dec   = (const float*)d_in[19];
    const float* Wphi_dec = (const float*)d_in[20];
    const float* bphi_dec = (const float*)d_in[21];
    const float* W_xmean  = (const float*)d_in[22];
    const float* b_xmean  = (const float*)d_in[23];
    const float* W_xstd   = (const float*)d_in[24];
    const float* b_xstd   = (const float*)d_in[25];
    float* out = (float*)d_out;

    float *p_xT, *p_gi, *p_h, *p_phi, *p_head, *p_z;
    float *p_WhZ, *p_bhZ, *p_WhX, *p_bhX;
    double *p_pz, *p_pn, *p_px;
    cudaGetSymbolAddress((void**)&p_xT,   g_xT);
    cudaGetSymbolAddress((void**)&p_gi,   g_gi);
    cudaGetSymbolAddress((void**)&p_h,    g_h);
    cudaGetSymbolAddress((void**)&p_phi,  g_phi);
    cudaGetSymbolAddress((void**)&p_head, g_head);
    cudaGetSymbolAddress((void**)&p_z,    g_z);
    cudaGetSymbolAddress((void**)&p_WhZ,  g_WheadZ);
    cudaGetSymbolAddress((void**)&p_bhZ,  g_bheadZ);
    cudaGetSymbolAddress((void**)&p_WhX,  g_WheadX);
    cudaGetSymbolAddress((void**)&p_bhX,  g_bheadX);
    cudaGetSymbolAddress((void**)&p_pz,   g_pz);
    cudaGetSymbolAddress((void**)&p_pn,   g_pn);
    cudaGetSymbolAddress((void**)&p_px,   g_px);

    cudaFuncSetAttribute(k_gru_scan, cudaFuncAttributeMaxDynamicSharedMemorySize, SCAN_SMEM);

    // 0) fused prep: transpose x, zero h0, pack head weights
    k_prep<<<(721152 + 255) / 256, 256>>>(x, W_zmean, b_zmean, W_zstd, b_zstd,
                                          W_xmean, b_xmean, W_xstd, b_xstd,
                                          p_xT, p_h, p_WhZ, p_bhZ, p_WhX, p_bhX);

    // 1) gi_enc = xT @ Wi_enc.T + bi_enc -> transposed [t][col][b]
    {
        dim3 grid(BT / 128, G / 128);
        k_gemm<<<grid, 256>>>(p_xT, Xd, Wi_enc, Xd, bi_enc, p_gi, G, Xd, 0, 1);
    }
    // 2) encoder GRU scan (persistent, b-split)
    k_gru_scan<<<NBLK, SCAN_THREADS, SCAN_SMEM>>>(p_gi, Wh_enc, bh_enc, p_h);

    // 3) phi_enc = relu(h_all @ Wphi_enc[:, :H].T + b)
    {
        dim3 grid(BT / 128, D / 128);
        k_gemm_ht<<<grid, 256>>>(p_h, Wphi_enc, H + Z, bphi_enc, p_phi, D, H, 1);
    }
    // 4) z heads (fused N=128 GEMM)
    {
        dim3 grid(BT / 128, 1);
        k_gemm<<<grid, 256>>>(p_phi, D, p_WhZ, D, p_bhZ, p_head, 128, D, 0, 0);
    }
    // 5) flow + z outputs + kld_z partials
    k_flow_enc<<<BT / 4, 256>>>(p_head, eps_enc, w_flow, b_flow, u_flow, out, p_z, p_pz);

    // 6) gi_dec = z_all @ Wi_dec.T + bi_dec -> transposed
    {
        dim3 grid(BT / 128, G / 128);
        k_gemm<<<grid, 256>>>(p_z, Z, Wi_dec, Z, bi_dec, p_gi, G, Z, 0, 1);
    }
    // 7) decoder GRU scan (h slab 0 still zero)
    k_gru_scan<<<NBLK, SCAN_THREADS, SCAN_SMEM>>>(p_gi, Wh_dec, bh_dec, p_h);

    // 8) phi_dec
    {
        dim3 grid(BT / 128, D / 128);
        k_gemm_ht<<<grid, 256>>>(p_h, Wphi_dec, H, bphi_dec, p_phi, D, H, 1);
    }
    // 9) x heads (fused)
    {
        dim3 grid(BT / 128, 1);
        k_gemm<<<grid, 256>>>(p_phi, D, p_WhX, D, p_bhX, p_head, 128, D, 0, 0);
    }
    // 10) decoder outputs + nll/kld_x partials
    k_dec_out<<<S / 256, 256>>>(p_head, eps_dec, x, out, p_pn, p_px);

    // 11) final reduction
    k_reduce_final<<<1, 256>>>(p_pz, p_pn, p_px, out);
}

// round 12
// speedup vs baseline: 1.0802x; 1.0802x over previous
#include <cuda_runtime.h>
#include <math.h>

// Problem dims
#define B   128
#define T   64
#define Xd  64
#define H   512
#define D   512
#define Z   64
#define KF  2
#define G   1536          // 3*H
#define BT  8192          // B*T
#define S   524288        // B*T*64
#define NBLK 128
#define SCAN_THREADS 512
#define SCAN_WARPS 16
#define SCAN_SMEM ((512*12 + SCAN_WARPS*12*128 + 16) * 4)

typedef unsigned long long ull;

// ---------------- scratch ----------------
__device__ float  g_xT[BT * Xd];           // x rearranged to [t*B+b][X]
__device__ float  g_gi[T * G * B];         // gi TRANSPOSED: [t][col][b]
__device__ float  g_h[(T + 1) * H * B];    // h TRANSPOSED: [t][k][b], slab 0 = zeros
__device__ float  g_phi[BT * D];
__device__ float  g_head[BT * 128];
__device__ float  g_z[BT * Z];
__device__ float  g_WheadZ[128 * 512];
__device__ float  g_bheadZ[128];
__device__ float  g_WheadX[128 * 512];
__device__ float  g_bheadX[128];
__device__ double g_pz[2048];              // kld_z partials (flow blocks)
__device__ double g_pn[2048];              // nll partials (dec_out blocks)
__device__ double g_px[2048];              // kld_x partials (dec_out blocks)
__device__ unsigned g_bar_count = 0;
__device__ unsigned g_bar_gen = 0;

// ---------------- helpers ----------------
__device__ __forceinline__ float sigmoidf_(float v) { return 1.0f / (1.0f + expf(-v)); }
__device__ __forceinline__ float softplusf_(float v) { return (v > 20.0f) ? v : log1pf(expf(v)); }
__device__ __forceinline__ float fsigmoid_(float v) { return 1.0f / (1.0f + __expf(-v)); }
__device__ __forceinline__ float ftanh_(float v) { return 1.0f - 2.0f / (__expf(2.0f * v) + 1.0f); }

__device__ __forceinline__ void fma2(ull &a, ull x, ull y) {
    asm("fma.rn.f32x2 %0, %1, %2, %0;" : "+l"(a) : "l"(x), "l"(y));
}
__device__ __forceinline__ ull pack2(float lo, float hi) {
    ull r;
    asm("mov.b64 %0, {%1, %2};" : "=l"(r) : "f"(lo), "f"(hi));
    return r;
}
__device__ __forceinline__ float2 unpack2(ull v) {
    float2 r;
    asm("mov.b64 {%0, %1}, %2;" : "=f"(r.x), "=f"(r.y) : "l"(v));
    return r;
}

// monotonic-counter grid barrier (no reset race); NBLK is a power of two
__device__ __forceinline__ void grid_barrier() {
    __threadfence();
    __syncthreads();
    if (threadIdx.x == 0) {
        volatile unsigned* vgen = &g_bar_gen;
        unsigned gen = *vgen;
        unsigned prev = atomicAdd(&g_bar_count, 1u);
        if ((prev & (NBLK - 1)) == (NBLK - 1)) {
            __threadfence();
            *vgen = gen + 1;
        } else {
            while (*vgen == gen) { }
            __threadfence();
        }
    }
    __syncthreads();
}

// ---------------- fused prep: transpose x, zero h0, pack both head weights ----------------
__global__ void k_prep(const float* __restrict__ x,
                       const float* __restrict__ Wzm, const float* __restrict__ bzm,
                       const float* __restrict__ Wzs, const float* __restrict__ bzs,
                       const float* __restrict__ Wxm, const float* __restrict__ bxm,
                       const float* __restrict__ Wxs, const float* __restrict__ bxs,
                       float* __restrict__ xT, float* __restrict__ h0,
                       float* __restrict__ WhZ, float* __restrict__ bhZ,
                       float* __restrict__ WhX, float* __restrict__ bhX) {
    int i = blockIdx.x * blockDim.x + threadIdx.x;
    if (i < 524288) {
        int b = i >> 12;
        int r = i & 4095;
        int t = r >> 6;
        int xi = r & 63;
        xT[((t << 7) + b) * Xd + xi] = x[i];
    } else if (i < 589824) {
        h0[i - 524288] = 0.0f;
    } else if (i < 622592) {
        int q = i - 589824; WhZ[q] = Wzm[q];
    } else if (i < 655360) {
        int q = i - 622592; WhZ[32768 + q] = Wzs[q];
    } else if (i < 688128) {
        int q = i - 655360; WhX[q] = Wxm[q];
    } else if (i < 720896) {
        int q = i - 688128; WhX[32768 + q] = Wxs[q];
    } else if (i < 721152) {
        int q = i - 720896;  // 0..255
        if (q < 64)        bhZ[q] = bzm[q];
        else if (q < 128)  bhZ[q] = bzs[q - 64];
        else if (q < 192)  bhX[q - 128] = bxm[q - 128];
        else               bhX[q - 128] = bxs[q - 192];
    }
}

// ---------------- tiled GEMM 128x128, 256 threads, 8x8 per thread ----------------
// Ping-pong double-buffered smem: ONE sync per k-tile. Conflict-free A reads.
__global__ void __launch_bounds__(256, 2)
k_gemm(const float* __restrict__ A, int lda,
       const float* __restrict__ W, int ldw,
       const float* __restrict__ bias,
       float* __restrict__ C, int ldc,
       int K, int act, int cmode) {
    __shared__ float As[2][16 * 132];
    __shared__ float Ws[2][16 * 132];
    const int m0 = blockIdx.x * 128;
    const int n0 = blockIdx.y * 128;
    const int tx = threadIdx.x >> 4;
    const int ty = threadIdx.x & 15;
    const int lm = threadIdx.x >> 1;
    const int lq = (threadIdx.x & 1) * 8;

    const float* Aptr = A + (size_t)(m0 + lm) * lda + lq;
    const float* Wptr = W + (size_t)(n0 + lm) * ldw + lq;

    ull acc[8][4];
    #pragma unroll
    for (int i = 0; i < 8; i++)
        #pragma unroll
        for (int j = 0; j < 4; j++) acc[i][j] = 0ull;

    // prologue: load tile 0, store to buffer 0
    {
        float4 a0 = *reinterpret_cast<const float4*>(Aptr);
        float4 a1 = *reinterpret_cast<const float4*>(Aptr + 4);
        float4 w0 = *reinterpret_cast<const float4*>(Wptr);
        float4 w1 = *reinterpret_cast<const float4*>(Wptr + 4);
        As[0][(lq + 0) * 132 + lm] = a0.x; As[0][(lq + 1) * 132 + lm] = a0.y;
        As[0][(lq + 2) * 132 + lm] = a0.z; As[0][(lq + 3) * 132 + lm] = a0.w;
        As[0][(lq + 4) * 132 + lm] = a1.x; As[0][(lq + 5) * 132 + lm] = a1.y;
        As[0][(lq + 6) * 132 + lm] = a1.z; As[0][(lq + 7) * 132 + lm] = a1.w;
        Ws[0][(lq + 0) * 132 + lm] = w0.x; Ws[0][(lq + 1) * 132 + lm] = w0.y;
        Ws[0][(lq + 2) * 132 + lm] = w0.z; Ws[0][(lq + 3) * 132 + lm] = w0.w;
        Ws[0][(lq + 4) * 132 + lm] = w1.x; Ws[0][(lq + 5) * 132 + lm] = w1.y;
        Ws[0][(lq + 6) * 132 + lm] = w1.z; Ws[0][(lq + 7) * 132 + lm] = w1.w;
    }
    __syncthreads();

    int p = 0;
    for (int k0 = 0; k0 < K; k0 += 16) {
        const bool more = (k0 + 16 < K);
        float4 a0, a1, w0, w1;
        if (more) {
            a0 = *reinterpret_cast<const float4*>(Aptr + k0 + 16);
            a1 = *reinterpret_cast<const float4*>(Aptr + k0 + 16 + 4);
            w0 = *reinterpret_cast<const float4*>(Wptr + k0 + 16);
            w1 = *reinterpret_cast<const float4*>(Wptr + k0 + 16 + 4);
        }
        const float* Asp = As[p];
        const float* Wsp = Ws[p];
        #pragma unroll
        for (int k = 0; k < 16; k++) {
            float am[8];
            #pragma unroll
            for (int mi = 0; mi < 8; mi++) am[mi] = Asp[k * 132 + ty + 16 * mi];
            ulonglong2 bn0 = *reinterpret_cast<const ulonglong2*>(Wsp + k * 132 + tx * 8);
            ulonglong2 bn1 = *reinterpret_cast<const ulonglong2*>(Wsp + k * 132 + tx * 8 + 4);
            ull bp[4] = {bn0.x, bn0.y, bn1.x, bn1.y};
            #pragma unroll
            for (int mi = 0; mi < 8; mi++) {
                ull a2 = pack2(am[mi], am[mi]);
                #pragma unroll
                for (int np = 0; np < 4; np++) fma2(acc[mi][np], a2, bp[np]);
            }
        }
        if (more) {
            int q = p ^ 1;
            As[q][(lq + 0) * 132 + lm] = a0.x; As[q][(lq + 1) * 132 + lm] = a0.y;
            As[q][(lq + 2) * 132 + lm] = a0.z; As[q][(lq + 3) * 132 + lm] = a0.w;
            As[q][(lq + 4) * 132 + lm] = a1.x; As[q][(lq + 5) * 132 + lm] = a1.y;
            As[q][(lq + 6) * 132 + lm] = a1.z; As[q][(lq + 7) * 132 + lm] = a1.w;
            Ws[q][(lq + 0) * 132 + lm] = w0.x; Ws[q][(lq + 1) * 132 + lm] = w0.y;
            Ws[q][(lq + 2) * 132 + lm] = w0.z; Ws[q][(lq + 3) * 132 + lm] = w0.w;
            Ws[q][(lq + 4) * 132 + lm] = w1.x; Ws[q][(lq + 5) * 132 + lm] = w1.y;
            Ws[q][(lq + 6) * 132 + lm] = w1.z; Ws[q][(lq + 7) * 132 + lm] = w1.w;
            __syncthreads();
            p = q;
        }
    }

    float cv[8][8];
    #pragma unroll
    for (int mi = 0; mi < 8; mi++) {
        #pragma unroll
        for (int np = 0; np < 4; np++) {
            float2 pv = unpack2(acc[mi][np]);
            float v0 = pv.x + bias[n0 + tx * 8 + 2 * np];
            float v1 = pv.y + bias[n0 + tx * 8 + 2 * np + 1];
            if (act == 1) { v0 = fmaxf(v0, 0.0f); v1 = fmaxf(v1, 0.0f); }
            cv[mi][2 * np] = v0; cv[mi][2 * np + 1] = v1;
        }
    }
    if (cmode == 0) {
        #pragma unroll
        for (int mi = 0; mi < 8; mi++) {
            int m = m0 + ty + 16 * mi;
            float4 s0 = make_float4(cv[mi][0], cv[mi][1], cv[mi][2], cv[mi][3]);
            float4 s1 = make_float4(cv[mi][4], cv[mi][5], cv[mi][6], cv[mi][7]);
            *reinterpret_cast<float4*>(C + (size_t)m * ldc + n0 + tx * 8)     = s0;
            *reinterpret_cast<float4*>(C + (size_t)m * ldc + n0 + tx * 8 + 4) = s1;
        }
    } else {
        const int t = blockIdx.x;          // m-tile == one full B
        #pragma unroll
        for (int j = 0; j < 8; j++) {
            int n = n0 + tx * 8 + j;
            size_t base = ((size_t)t * ldc + n) * B;
            #pragma unroll
            for (int mi = 0; mi < 8; mi++)
                C[base + ty + 16 * mi] = cv[mi][j];
        }
    }
}

// ---------------- GEMM variant: A from transposed h [(t+1)][k][b], ping-pong ----------------
__global__ void __launch_bounds__(256, 2)
k_gemm_ht(const float* __restrict__ hT,
          const float* __restrict__ W, int ldw,
          const float* __restrict__ bias,
          float* __restrict__ C, int ldc,
          int K, int act) {
    __shared__ float As[2][16 * 132];
    __shared__ float Ws[2][16 * 132];
    const int m0 = blockIdx.x * 128;
    const int n0 = blockIdx.y * 128;
    const size_t slab = (size_t)(blockIdx.x + 1) * (H * B);
    const int tx = threadIdx.x >> 4;
    const int ty = threadIdx.x & 15;
    const int lm = threadIdx.x >> 1;
    const int lq = (threadIdx.x & 1) * 8;
    const int lk = threadIdx.x >> 4;
    const int lb = (threadIdx.x & 15) * 8;

    const float* Hptr = hT + slab + (size_t)lk * B + lb;
    const float* Wptr = W + (size_t)(n0 + lm) * ldw + lq;

    ull acc[8][4];
    #pragma unroll
    for (int i = 0; i < 8; i++)
        #pragma unroll
        for (int j = 0; j < 4; j++) acc[i][j] = 0ull;

    {
        float4 h0 = *reinterpret_cast<const float4*>(Hptr);
        float4 h1 = *reinterpret_cast<const float4*>(Hptr + 4);
        float4 w0 = *reinterpret_cast<const float4*>(Wptr);
        float4 w1 = *reinterpret_cast<const float4*>(Wptr + 4);
        *reinterpret_cast<float4*>(&As[0][lk * 132 + lb])     = h0;
        *reinterpret_cast<float4*>(&As[0][lk * 132 + lb + 4]) = h1;
        Ws[0][(lq + 0) * 132 + lm] = w0.x; Ws[0][(lq + 1) * 132 + lm] = w0.y;
        Ws[0][(lq + 2) * 132 + lm] = w0.z; Ws[0][(lq + 3) * 132 + lm] = w0.w;
        Ws[0][(lq + 4) * 132 + lm] = w1.x; Ws[0][(lq + 5) * 132 + lm] = w1.y;
        Ws[0][(lq + 6) * 132 + lm] = w1.z; Ws[0][(lq + 7) * 132 + lm] = w1.w;
    }
    __syncthreads();

    int p = 0;
    for (int k0 = 0; k0 < K; k0 += 16) {
        const bool more = (k0 + 16 < K);
        float4 h0, h1, w0, w1;
        if (more) {
            h0 = *reinterpret_cast<const float4*>(Hptr + (size_t)(k0 + 16) * B);
            h1 = *reinterpret_cast<const float4*>(Hptr + (size_t)(k0 + 16) * B + 4);
            w0 = *reinterpret_cast<const float4*>(Wptr + k0 + 16);
            w1 = *reinterpret_cast<const float4*>(Wptr + k0 + 16 + 4);
        }
        const float* Asp = As[p];
        const float* Wsp = Ws[p];
        #pragma unroll
        for (int k = 0; k < 16; k++) {
            float am[8];
            #pragma unroll
            for (int mi = 0; mi < 8; mi++) am[mi] = Asp[k * 132 + ty + 16 * mi];
            ulonglong2 bn0 = *reinterpret_cast<const ulonglong2*>(Wsp + k * 132 + tx * 8);
            ulonglong2 bn1 = *reinterpret_cast<const ulonglong2*>(Wsp + k * 132 + tx * 8 + 4);
            ull bp[4] = {bn0.x, bn0.y, bn1.x, bn1.y};
            #pragma unroll
            for (int mi = 0; mi < 8; mi++) {
                ull a2 = pack2(am[mi], am[mi]);
                #pragma unroll
                for (int np = 0; np < 4; np++) fma2(acc[mi][np], a2, bp[np]);
            }
        }
        if (more) {
            int q = p ^ 1;
            *reinterpret_cast<float4*>(&As[q][lk * 132 + lb])     = h0;
            *reinterpret_cast<float4*>(&As[q][lk * 132 + lb + 4]) = h1;
            Ws[q][(lq + 0) * 132 + lm] = w0.x; Ws[q][(lq + 1) * 132 + lm] = w0.y;
            Ws[q][(lq + 2) * 132 + lm] = w0.z; Ws[q][(lq + 3) * 132 + lm] = w0.w;
            Ws[q][(lq + 4) * 132 + lm] = w1.x; Ws[q][(lq + 5) * 132 + lm] = w1.y;
            Ws[q][(lq + 6) * 132 + lm] = w1.z; Ws[q][(lq + 7) * 132 + lm] = w1.w;
            __syncthreads();
            p = q;
        }
    }
    #pragma unroll
    for (int mi = 0; mi < 8; mi++) {
        int m = m0 + ty + 16 * mi;
        float cv[8];
        #pragma unroll
        for (int np = 0; np < 4; np++) {
            float2 pv = unpack2(acc[mi][np]);
            float v0 = pv.x + bias[n0 + tx * 8 + 2 * np];
            float v1 = pv.y + bias[n0 + tx * 8 + 2 * np + 1];
            if (act == 1) { v0 = fmaxf(v0, 0.0f); v1 = fmaxf(v1, 0.0f); }
            cv[2 * np] = v0; cv[2 * np + 1] = v1;
        }
        float4 s0 = make_float4(cv[0], cv[1], cv[2], cv[3]);
        float4 s1 = make_float4(cv[4], cv[5], cv[6], cv[7]);
        *reinterpret_cast<float4*>(C + (size_t)m * ldc + n0 + tx * 8)     = s0;
        *reinterpret_cast<float4*>(C + (size_t)m * ldc + n0 + tx * 8 + 4) = s1;
    }
}

// ---------------- persistent GRU scan (exact R10 structure) ----------------
extern __shared__ float smem_dyn[];

__global__ void __launch_bounds__(SCAN_THREADS, 1)
k_gru_scan(const float* __restrict__ giT,  // [T][G][B]
           const float* __restrict__ Wh,   // [G, H]
           const float* __restrict__ bh,   // [G]
           float* __restrict__ hT)         // [(T+1), H, B]
{
    float* ws  = smem_dyn;                     // [512][12] : ws[k*12 + c], c = g*4+jj
    float* red = ws + 512 * 12;                // [16][12][128]
    float* sbh = red + SCAN_WARPS * 12 * 128;  // [12]
    const int tid  = threadIdx.x;
    const int warp = tid >> 5;
    const int lane = tid & 31;
    const int j0   = blockIdx.x * 4;

    for (int i = tid; i < 12 * 512; i += SCAN_THREADS) {
        int c = i >> 9, k = i & 511;
        ws[k * 12 + c] = Wh[((size_t)((c >> 2) * H + j0 + (c & 3))) * H + k];
    }
    if (tid < 12) sbh[tid] = bh[(tid >> 2) * H + j0 + (tid & 3)];
    __syncthreads();

    const int k0 = warp * 32;
    const int bbase = lane * 4;
    const int gjj = tid >> 7;       // gate-phase j
    const int gb  = tid & 127;      // gate-phase b
    const float bias_r = sbh[gjj];
    const float bias_z = sbh[4 + gjj];
    const float bias_n = sbh[8 + gjj];

    for (int t = 0; t < T; t++) {
        const float* hprev = hT + (size_t)t * (H * B);

        // prefetch gate-phase operands (coalesced; completes under the k-loop)
        size_t gibase = ((size_t)t * G + j0 + gjj) * B + gb;
        float ir  = giT[gibase];
        float iz  = giT[gibase + (size_t)H * B];
        float inn = giT[gibase + (size_t)2 * H * B];
        float hp  = hprev[(size_t)(j0 + gjj) * B + gb];

        ull acc[4][6];
        #pragma unroll
        for (int i = 0; i < 4; i++)
            #pragma unroll
            for (int cp = 0; cp < 6; cp++) acc[i][cp] = 0ull;

        #pragma unroll 4
        for (int kk = 0; kk < 32; kk++) {
            int k = k0 + kk;
            float4 hv = *reinterpret_cast<const float4*>(hprev + (size_t)k * B + bbase);
            ull h2[4];
            h2[0] = pack2(hv.x, hv.x);
            h2[1] = pack2(hv.y, hv.y);
            h2[2] = pack2(hv.z, hv.z);
            h2[3] = pack2(hv.w, hv.w);
            const float* wrow = ws + k * 12;
            #pragma unroll
            for (int cp = 0; cp < 6; cp++) {
                ull w2 = *reinterpret_cast<const ull*>(wrow + cp * 2);
                #pragma unroll
                for (int i = 0; i < 4; i++) fma2(acc[i][cp], h2[i], w2);
            }
        }

        #pragma unroll
        for (int cp = 0; cp < 6; cp++) {
            float2 v0 = unpack2(acc[0][cp]);
            float2 v1 = unpack2(acc[1][cp]);
            float2 v2 = unpack2(acc[2][cp]);
            float2 v3 = unpack2(acc[3][cp]);
            float4 a  = make_float4(v0.x, v1.x, v2.x, v3.x);
            float4 b4 = make_float4(v0.y, v1.y, v2.y, v3.y);
            *reinterpret_cast<float4*>(red + ((size_t)(warp * 12 + 2 * cp)) * B + bbase)     = a;
            *reinterpret_cast<float4*>(red + ((size_t)(warp * 12 + 2 * cp + 1)) * B + bbase) = b4;
        }
        __syncthreads();

        // gate phase: 512 outputs, one per thread
        {
            float gr = 0.f, gz = 0.f, gn = 0.f;
            #pragma unroll
            for (int w = 0; w < SCAN_WARPS; w++) {
                gr += red[(w * 12 + 0 + gjj) * B + gb];
                gz += red[(w * 12 + 4 + gjj) * B + gb];
                gn += red[(w * 12 + 8 + gjj) * B + gb];
            }
            float r = fsigmoid_(ir + gr + bias_r);
            float u = fsigmoid_(iz + gz + bias_z);
            float n = ftanh_(inn + r * (gn + bias_n));
            hT[((size_t)(t + 1) * H + j0 + gjj) * B + gb] = (1.0f - u) * n + u * hp;
        }

        grid_barrier();
    }
}

// ---------------- encoder output: zm, zs, z, planar flow + kld_z partials ----------------
__global__ void k_flow_enc(const float* __restrict__ head,
                           const float* __restrict__ eps_enc,
                           const float* __restrict__ w_flow,
                           const float* __restrict__ b_flow,
                           const float* __restrict__ u_flow,
                           float* __restrict__ out,
                           float* __restrict__ z_all,
                           double* __restrict__ pz) {
    __shared__ float red[4][64];
    __shared__ double dred[256];
    int rl = threadIdx.x >> 6;
    int j = threadIdx.x & 63;
    int row = blockIdx.x * 4 + rl;       // t*B + b
    int t = row >> 7;
    int b = row & 127;

    float zm = sigmoidf_(head[row * 128 + j]);
    float zs = softplusf_(head[row * 128 + 64 + j]);
    float eps = eps_enc[b * (T * Z) + t * Z + j];
    float z = eps * zs + zm;

    #pragma unroll
    for (int k = 0; k < KF; k++) {
        red[rl][j] = z * w_flow[(t * KF + k) * Z + j];
        __syncthreads();
        #pragma unroll
        for (int s = 32; s > 0; s >>= 1) {
            if (j < s) red[rl][j] += red[rl][j + s];
            __syncthreads();
        }
        float sv = red[rl][0] + b_flow[t * KF + k];
        __syncthreads();
        z += u_flow[(t * KF + k) * Z + j] * tanhf(sv);
    }

    int o = (b * T + t) * Z + j;
    out[2 + o]         = z;
    out[2 + S + o]     = zm;
    out[2 + 2 * S + o] = zs;
    z_all[row * Z + j] = z;

    // kld_z partial: 1 + zs - zm^2 - exp(zs) (float exp, double accumulate)
    float ez = expf(zs);
    dred[threadIdx.x] = 1.0 + (double)zs - (double)zm * (double)zm - (double)ez;
    __syncthreads();
    for (int s = 128; s > 0; s >>= 1) {
        if (threadIdx.x < s) dred[threadIdx.x] += dred[threadIdx.x + s];
        __syncthreads();
    }
    if (threadIdx.x == 0) pz[blockIdx.x] = dred[0];
}

// ---------------- decoder output + nll/kld_x partials ----------------
__global__ void k_dec_out(const float* __restrict__ head,
                          const float* __restrict__ eps_dec,
                          const float* __restrict__ x,
                          float* __restrict__ out,
                          double* __restrict__ pn,
                          double* __restrict__ px) {
    __shared__ double sn[256];
    __shared__ double sk[256];
    int i = blockIdx.x * blockDim.x + threadIdx.x;
    int row = i >> 6;
    int j = i & 63;
    int t = row >> 7;
    int b = row & 127;
    float xm = sigmoidf_(head[row * 128 + j]);
    float xs = softplusf_(head[row * 128 + 64 + j]);
    int src = b * (T * Xd) + t * Xd + j;
    float eps = eps_dec[src];
    float xo = eps * xs + xm;
    int o = (b * T + t) * Xd + j;
    out[2 + 3 * S + o] = xo;
    out[2 + 4 * S + o] = xm;
    out[2 + 5 * S + o] = xs;

    float xv = x[src];
    float dq = (xv - xm) * expf(-0.5f * xs);
    float ex = expf(xs);
    sn[threadIdx.x] = (double)xs + (double)dq * (double)dq;
    sk[threadIdx.x] = 1.0 + (double)xs - (double)xm * (double)xm - (double)ex;
    __syncthreads();
    for (int s = 128; s > 0; s >>= 1) {
        if (threadIdx.x < s) {
            sn[threadIdx.x] += sn[threadIdx.x + s];
            sk[threadIdx.x] += sk[threadIdx.x + s];
        }
        __syncthreads();
    }
    if (threadIdx.x == 0) {
        pn[blockIdx.x] = sn[0];
        px[blockIdx.x] = sk[0];
    }
}

// ---------------- final deterministic reduction ----------------
__global__ void k_reduce_final(const double* __restrict__ pz,
                               const double* __restrict__ pn,
                               const double* __restrict__ px,
                               float* __restrict__ out) {
    __shared__ double sn[256];
    __shared__ double sk[256];
    double an = 0.0, ak = 0.0;
    for (int i = threadIdx.x; i < 2048; i += 256) {
        an += pn[i];
        ak += pz[i] + px[i];
    }
    sn[threadIdx.x] = an;
    sk[threadIdx.x] = ak;
    __syncthreads();
    for (int s = 128; s > 0; s >>= 1) {
        if (threadIdx.x < s) {
            sn[threadIdx.x] += sn[threadIdx.x + s];
            sk[threadIdx.x] += sk[threadIdx.x + s];
        }
        __syncthreads();
    }
    if (threadIdx.x == 0) {
        out[0] = (float)(0.5 * sn[0]);
        out[1] = (float)(-0.5 * sk[0]);
    }
}

// ---------------- launch ----------------
extern "C" void kernel_launch(void* const* d_in, const int* in_sizes, int n_in,
                              void* d_out, int out_size) {
    const float* x        = (const float*)d_in[0];
    const float* eps_enc  = (const float*)d_in[1];
    const float* eps_dec  = (const float*)d_in[2];
    const float* Wi_enc   = (const float*)d_in[3];
    const float* Wh_enc   = (const float*)d_in[4];
    const float* bi_enc   = (const float*)d_in[5];
    const float* bh_enc   = (const float*)d_in[6];
    const float* Wphi_enc = (const float*)d_in[7];
    const float* bphi_enc = (const float*)d_in[8];
    const float* W_zmean  = (const float*)d_in[9];
    const float* b_zmean  = (const float*)d_in[10];
    const float* W_zstd   = (const float*)d_in[11];
    const float* b_zstd   = (const float*)d_in[12];
    const float* w_flow   = (const float*)d_in[13];
    const float* b_flow   = (const float*)d_in[14];
    const float* u_flow   = (const float*)d_in[15];
    const float* Wi_dec   = (const float*)d_in[16];
    const float* Wh_dec   = (const float*)d_in[17];
    const float* bi_dec   = (const float*)d_in[18];
    const float* bh_dec   = (const float*)d_in[19];
    const float* Wphi_dec = (const float*)d_in[20];
    const float* bphi_dec = (const float*)d_in[21];
    const float* W_xmean  = (const float*)d_in[22];
    const float* b_xmean  = (const float*)d_in[23];
    const float* W_xstd   = (const float*)d_in[24];
    const float* b_xstd   = (const float*)d_in[25];
    float* out = (float*)d_out;

    float *p_xT, *p_gi, *p_h, *p_phi, *p_head, *p_z;
    float *p_WhZ, *p_bhZ, *p_WhX, *p_bhX;
    double *p_pz, *p_pn, *p_px;
    cudaGetSymbolAddress((void**)&p_xT,   g_xT);
    cudaGetSymbolAddress((void**)&p_gi,   g_gi);
    cudaGetSymbolAddress((void**)&p_h,    g_h);
    cudaGetSymbolAddress((void**)&p_phi,  g_phi);
    cudaGetSymbolAddress((void**)&p_head, g_head);
    cudaGetSymbolAddress((void**)&p_z,    g_z);
    cudaGetSymbolAddress((void**)&p_WhZ,  g_WheadZ);
    cudaGetSymbolAddress((void**)&p_bhZ,  g_bheadZ);
    cudaGetSymbolAddress((void**)&p_WhX,  g_WheadX);
    cudaGetSymbolAddress((void**)&p_bhX,  g_bheadX);
    cudaGetSymbolAddress((void**)&p_pz,   g_pz);
    cudaGetSymbolAddress((void**)&p_pn,   g_pn);
    cudaGetSymbolAddress((void**)&p_px,   g_px);

    cudaFuncSetAttribute(k_gru_scan, cudaFuncAttributeMaxDynamicSharedMemorySize, SCAN_SMEM);

    // 0) fused prep: transpose x, zero h0, pack head weights
    k_prep<<<(721152 + 255) / 256, 256>>>(x, W_zmean, b_zmean, W_zstd, b_zstd,
                                          W_xmean, b_xmean, W_xstd, b_xstd,
                                          p_xT, p_h, p_WhZ, p_bhZ, p_WhX, p_bhX);

    // 1) gi_enc = xT @ Wi_enc.T + bi_enc -> transposed [t][col][b]
    {
        dim3 grid(BT / 128, G / 128);
        k_gemm<<<grid, 256>>>(p_xT, Xd, Wi_enc, Xd, bi_enc, p_gi, G, Xd, 0, 1);
    }
    // 2) encoder GRU scan (persistent)
    k_gru_scan<<<NBLK, SCAN_THREADS, SCAN_SMEM>>>(p_gi, Wh_enc, bh_enc, p_h);

    // 3) phi_enc = relu(h_all @ Wphi_enc[:, :H].T + b)
    {
        dim3 grid(BT / 128, D / 128);
        k_gemm_ht<<<grid, 256>>>(p_h, Wphi_enc, H + Z, bphi_enc, p_phi, D, H, 1);
    }
    // 4) z heads (fused N=128 GEMM)
    {
        dim3 grid(BT / 128, 1);
        k_gemm<<<grid, 256>>>(p_phi, D, p_WhZ, D, p_bhZ, p_head, 128, D, 0, 0);
    }
    // 5) flow + z outputs + kld_z partials
    k_flow_enc<<<BT / 4, 256>>>(p_head, eps_enc, w_flow, b_flow, u_flow, out, p_z, p_pz);

    // 6) gi_dec = z_all @ Wi_dec.T + bi_dec -> transposed
    {
        dim3 grid(BT / 128, G / 128);
        k_gemm<<<grid, 256>>>(p_z, Z, Wi_dec, Z, bi_dec, p_gi, G, Z, 0, 1);
    }
    // 7) decoder GRU scan (h slab 0 still zero)
    k_gru_scan<<<NBLK, SCAN_THREADS, SCAN_SMEM>>>(p_gi, Wh_dec, bh_dec, p_h);

    // 8) phi_dec
    {
        dim3 grid(BT / 128, D / 128);
        k_gemm_ht<<<grid, 256>>>(p_h, Wphi_dec, H, bphi_dec, p_phi, D, H, 1);
    }
    // 9) x heads (fused)
    {
        dim3 grid(BT / 128, 1);
        k_gemm<<<grid, 256>>>(p_phi, D, p_WhX, D, p_bhX, p_head, 128, D, 0, 0);
    }
    // 10) decoder outputs + nll/kld_x partials
    k_dec_out<<<S / 256, 256>>>(p_head, eps_dec, x, out, p_pn, p_px);

    // 11) final reduction
    k_reduce_final<<<1, 256>>>(p_pz, p_pn, p_px, out);
}

// round 13
// speedup vs baseline: 1.1051x; 1.0230x over previous
#include <cuda_runtime.h>
#include <math.h>

// Problem dims
#define B   128
#define T   64
#define Xd  64
#define H   512
#define D   512
#define Z   64
#define KF  2
#define G   1536          // 3*H
#define BT  8192          // B*T
#define S   524288        // B*T*64
#define NBLK 128
#define SCAN_THREADS 512
#define SCAN_WARPS 16
#define SCAN_SMEM ((512*12 + SCAN_WARPS*12*128 + 16) * 4)

typedef unsigned long long ull;

// ---------------- scratch ----------------
__device__ float  g_xT[BT * Xd];           // x rearranged to [t*B+b][X]
__device__ float  g_gi[T * G * B];         // gi TRANSPOSED: [t][col][b]
__device__ float  g_h[(T + 1) * H * B];    // h TRANSPOSED: [t][k][b], slab 0 = zeros
__device__ float  g_phi[BT * D];
__device__ float  g_head[BT * 128];
__device__ float  g_z[BT * Z];
__device__ float  g_WheadZ[128 * 512];
__device__ float  g_bheadZ[128];
__device__ float  g_WheadX[128 * 512];
__device__ float  g_bheadX[128];
__device__ double g_pz[2048];              // kld_z partials (flow blocks)
__device__ double g_pn[2048];              // nll partials (dec_out blocks)
__device__ double g_px[2048];              // kld_x partials (dec_out blocks)
__device__ unsigned g_bar_count = 0;
__device__ unsigned g_bar_gen = 0;

// ---------------- helpers ----------------
__device__ __forceinline__ float sigmoidf_(float v) { return 1.0f / (1.0f + expf(-v)); }
__device__ __forceinline__ float softplusf_(float v) { return (v > 20.0f) ? v : log1pf(expf(v)); }
__device__ __forceinline__ float fsigmoid_(float v) { return 1.0f / (1.0f + __expf(-v)); }
__device__ __forceinline__ float ftanh_(float v) { return 1.0f - 2.0f / (__expf(2.0f * v) + 1.0f); }

__device__ __forceinline__ void fma2(ull &a, ull x, ull y) {
    asm("fma.rn.f32x2 %0, %1, %2, %0;" : "+l"(a) : "l"(x), "l"(y));
}
__device__ __forceinline__ ull pack2(float lo, float hi) {
    ull r;
    asm("mov.b64 %0, {%1, %2};" : "=l"(r) : "f"(lo), "f"(hi));
    return r;
}
__device__ __forceinline__ float2 unpack2(ull v) {
    float2 r;
    asm("mov.b64 {%0, %1}, %2;" : "=f"(r.x), "=f"(r.y) : "l"(v));
    return r;
}

// monotonic-counter grid barrier (no reset race); NBLK is a power of two
__device__ __forceinline__ void grid_barrier() {
    __threadfence();
    __syncthreads();
    if (threadIdx.x == 0) {
        volatile unsigned* vgen = &g_bar_gen;
        unsigned gen = *vgen;
        unsigned prev = atomicAdd(&g_bar_count, 1u);
        if ((prev & (NBLK - 1)) == (NBLK - 1)) {
            __threadfence();
            *vgen = gen + 1;
        } else {
            while (*vgen == gen) { }
            __threadfence();
        }
    }
    __syncthreads();
}

// ---------------- fused prep: transpose x, zero h0, pack both head weights ----------------
__global__ void k_prep(const float* __restrict__ x,
                       const float* __restrict__ Wzm, const float* __restrict__ bzm,
                       const float* __restrict__ Wzs, const float* __restrict__ bzs,
                       const float* __restrict__ Wxm, const float* __restrict__ bxm,
                       const float* __restrict__ Wxs, const float* __restrict__ bxs,
                       float* __restrict__ xT, float* __restrict__ h0,
                       float* __restrict__ WhZ, float* __restrict__ bhZ,
                       float* __restrict__ WhX, float* __restrict__ bhX) {
    int i = blockIdx.x * blockDim.x + threadIdx.x;
    if (i < 524288) {
        int b = i >> 12;
        int r = i & 4095;
        int t = r >> 6;
        int xi = r & 63;
        xT[((t << 7) + b) * Xd + xi] = x[i];
    } else if (i < 589824) {
        h0[i - 524288] = 0.0f;
    } else if (i < 622592) {
        int q = i - 589824; WhZ[q] = Wzm[q];
    } else if (i < 655360) {
        int q = i - 622592; WhZ[32768 + q] = Wzs[q];
    } else if (i < 688128) {
        int q = i - 655360; WhX[q] = Wxm[q];
    } else if (i < 720896) {
        int q = i - 688128; WhX[32768 + q] = Wxs[q];
    } else if (i < 721152) {
        int q = i - 720896;  // 0..255
        if (q < 64)        bhZ[q] = bzm[q];
        else if (q < 128)  bhZ[q] = bzs[q - 64];
        else if (q < 192)  bhX[q - 128] = bxm[q - 128];
        else               bhX[q - 128] = bxs[q - 192];
    }
}

// ---------------- tiled GEMM 128x128, 256 threads, 8x8 per thread ----------------
// Ping-pong double-buffered, A reads as paired LDS.64 (m = 2*ty + 32*mi + half).
__global__ void __launch_bounds__(256, 2)
k_gemm(const float* __restrict__ A, int lda,
       const float* __restrict__ W, int ldw,
       const float* __restrict__ bias,
       float* __restrict__ C, int ldc,
       int K, int act, int cmode) {
    __shared__ float As[2][16 * 132];
    __shared__ float Ws[2][16 * 132];
    const int m0 = blockIdx.x * 128;
    const int n0 = blockIdx.y * 128;
    const int tx = threadIdx.x >> 4;
    const int ty = threadIdx.x & 15;
    const int lm = threadIdx.x >> 1;
    const int lq = (threadIdx.x & 1) * 8;

    const float* Aptr = A + (size_t)(m0 + lm) * lda + lq;
    const float* Wptr = W + (size_t)(n0 + lm) * ldw + lq;

    ull acc[8][4];
    #pragma unroll
    for (int i = 0; i < 8; i++)
        #pragma unroll
        for (int j = 0; j < 4; j++) acc[i][j] = 0ull;

    {
        float4 a0 = *reinterpret_cast<const float4*>(Aptr);
        float4 a1 = *reinterpret_cast<const float4*>(Aptr + 4);
        float4 w0 = *reinterpret_cast<const float4*>(Wptr);
        float4 w1 = *reinterpret_cast<const float4*>(Wptr + 4);
        As[0][(lq + 0) * 132 + lm] = a0.x; As[0][(lq + 1) * 132 + lm] = a0.y;
        As[0][(lq + 2) * 132 + lm] = a0.z; As[0][(lq + 3) * 132 + lm] = a0.w;
        As[0][(lq + 4) * 132 + lm] = a1.x; As[0][(lq + 5) * 132 + lm] = a1.y;
        As[0][(lq + 6) * 132 + lm] = a1.z; As[0][(lq + 7) * 132 + lm] = a1.w;
        Ws[0][(lq + 0) * 132 + lm] = w0.x; Ws[0][(lq + 1) * 132 + lm] = w0.y;
        Ws[0][(lq + 2) * 132 + lm] = w0.z; Ws[0][(lq + 3) * 132 + lm] = w0.w;
        Ws[0][(lq + 4) * 132 + lm] = w1.x; Ws[0][(lq + 5) * 132 + lm] = w1.y;
        Ws[0][(lq + 6) * 132 + lm] = w1.z; Ws[0][(lq + 7) * 132 + lm] = w1.w;
    }
    __syncthreads();

    int p = 0;
    for (int k0 = 0; k0 < K; k0 += 16) {
        const bool more = (k0 + 16 < K);
        float4 a0, a1, w0, w1;
        if (more) {
            a0 = *reinterpret_cast<const float4*>(Aptr + k0 + 16);
            a1 = *reinterpret_cast<const float4*>(Aptr + k0 + 16 + 4);
            w0 = *reinterpret_cast<const float4*>(Wptr + k0 + 16);
            w1 = *reinterpret_cast<const float4*>(Wptr + k0 + 16 + 4);
        }
        const float* Asp = As[p];
        const float* Wsp = Ws[p];
        #pragma unroll
        for (int k = 0; k < 16; k++) {
            // A: paired LDS.64, m = 2*ty + 32*mi + {0,1} (conflict-free, stride-2 banks)
            float2 ap[4];
            #pragma unroll
            for (int mi = 0; mi < 4; mi++)
                ap[mi] = *reinterpret_cast<const float2*>(Asp + k * 132 + 2 * ty + 32 * mi);
            ulonglong2 bn0 = *reinterpret_cast<const ulonglong2*>(Wsp + k * 132 + tx * 8);
            ulonglong2 bn1 = *reinterpret_cast<const ulonglong2*>(Wsp + k * 132 + tx * 8 + 4);
            ull bp[4] = {bn0.x, bn0.y, bn1.x, bn1.y};
            #pragma unroll
            for (int mi = 0; mi < 4; mi++) {
                ull ax = pack2(ap[mi].x, ap[mi].x);
                ull ay = pack2(ap[mi].y, ap[mi].y);
                #pragma unroll
                for (int np = 0; np < 4; np++) {
                    fma2(acc[2 * mi][np],     ax, bp[np]);
                    fma2(acc[2 * mi + 1][np], ay, bp[np]);
                }
            }
        }
        if (more) {
            int q = p ^ 1;
            As[q][(lq + 0) * 132 + lm] = a0.x; As[q][(lq + 1) * 132 + lm] = a0.y;
            As[q][(lq + 2) * 132 + lm] = a0.z; As[q][(lq + 3) * 132 + lm] = a0.w;
            As[q][(lq + 4) * 132 + lm] = a1.x; As[q][(lq + 5) * 132 + lm] = a1.y;
            As[q][(lq + 6) * 132 + lm] = a1.z; As[q][(lq + 7) * 132 + lm] = a1.w;
            Ws[q][(lq + 0) * 132 + lm] = w0.x; Ws[q][(lq + 1) * 132 + lm] = w0.y;
            Ws[q][(lq + 2) * 132 + lm] = w0.z; Ws[q][(lq + 3) * 132 + lm] = w0.w;
            Ws[q][(lq + 4) * 132 + lm] = w1.x; Ws[q][(lq + 5) * 132 + lm] = w1.y;
            Ws[q][(lq + 6) * 132 + lm] = w1.z; Ws[q][(lq + 7) * 132 + lm] = w1.w;
            __syncthreads();
            p = q;
        }
    }

    float cv[8][8];   // cv[2*mi+half][n]
    #pragma unroll
    for (int r = 0; r < 8; r++) {
        #pragma unroll
        for (int np = 0; np < 4; np++) {
            float2 pv = unpack2(acc[r][np]);
            float v0 = pv.x + bias[n0 + tx * 8 + 2 * np];
            float v1 = pv.y + bias[n0 + tx * 8 + 2 * np + 1];
            if (act == 1) { v0 = fmaxf(v0, 0.0f); v1 = fmaxf(v1, 0.0f); }
            cv[r][2 * np] = v0; cv[r][2 * np + 1] = v1;
        }
    }
    if (cmode == 0) {
        #pragma unroll
        for (int r = 0; r < 8; r++) {
            int m = m0 + 2 * ty + 32 * (r >> 1) + (r & 1);
            float4 s0 = make_float4(cv[r][0], cv[r][1], cv[r][2], cv[r][3]);
            float4 s1 = make_float4(cv[r][4], cv[r][5], cv[r][6], cv[r][7]);
            *reinterpret_cast<float4*>(C + (size_t)m * ldc + n0 + tx * 8)     = s0;
            *reinterpret_cast<float4*>(C + (size_t)m * ldc + n0 + tx * 8 + 4) = s1;
        }
    } else {
        const int t = blockIdx.x;          // m-tile == one full B
        #pragma unroll
        for (int j = 0; j < 8; j++) {
            int n = n0 + tx * 8 + j;
            size_t base = ((size_t)t * ldc + n) * B;
            #pragma unroll
            for (int r = 0; r < 8; r += 2) {
                int m = 2 * ty + 32 * (r >> 1);
                *reinterpret_cast<float2*>(C + base + m) = make_float2(cv[r][j], cv[r + 1][j]);
            }
        }
    }
}

// ---------------- GEMM variant: A from transposed h [(t+1)][k][b], ping-pong ----------------
__global__ void __launch_bounds__(256, 2)
k_gemm_ht(const float* __restrict__ hT,
          const float* __restrict__ W, int ldw,
          const float* __restrict__ bias,
          float* __restrict__ C, int ldc,
          int K, int act) {
    __shared__ float As[2][16 * 132];
    __shared__ float Ws[2][16 * 132];
    const int m0 = blockIdx.x * 128;
    const int n0 = blockIdx.y * 128;
    const size_t slab = (size_t)(blockIdx.x + 1) * (H * B);
    const int tx = threadIdx.x >> 4;
    const int ty = threadIdx.x & 15;
    const int lm = threadIdx.x >> 1;
    const int lq = (threadIdx.x & 1) * 8;
    const int lk = threadIdx.x >> 4;
    const int lb = (threadIdx.x & 15) * 8;

    const float* Hptr = hT + slab + (size_t)lk * B + lb;
    const float* Wptr = W + (size_t)(n0 + lm) * ldw + lq;

    ull acc[8][4];
    #pragma unroll
    for (int i = 0; i < 8; i++)
        #pragma unroll
        for (int j = 0; j < 4; j++) acc[i][j] = 0ull;

    {
        float4 h0 = *reinterpret_cast<const float4*>(Hptr);
        float4 h1 = *reinterpret_cast<const float4*>(Hptr + 4);
        float4 w0 = *reinterpret_cast<const float4*>(Wptr);
        float4 w1 = *reinterpret_cast<const float4*>(Wptr + 4);
        *reinterpret_cast<float4*>(&As[0][lk * 132 + lb])     = h0;
        *reinterpret_cast<float4*>(&As[0][lk * 132 + lb + 4]) = h1;
        Ws[0][(lq + 0) * 132 + lm] = w0.x; Ws[0][(lq + 1) * 132 + lm] = w0.y;
        Ws[0][(lq + 2) * 132 + lm] = w0.z; Ws[0][(lq + 3) * 132 + lm] = w0.w;
        Ws[0][(lq + 4) * 132 + lm] = w1.x; Ws[0][(lq + 5) * 132 + lm] = w1.y;
        Ws[0][(lq + 6) * 132 + lm] = w1.z; Ws[0][(lq + 7) * 132 + lm] = w1.w;
    }
    __syncthreads();

    int p = 0;
    for (int k0 = 0; k0 < K; k0 += 16) {
        const bool more = (k0 + 16 < K);
        float4 h0, h1, w0, w1;
        if (more) {
            h0 = *reinterpret_cast<const float4*>(Hptr + (size_t)(k0 + 16) * B);
            h1 = *reinterpret_cast<const float4*>(Hptr + (size_t)(k0 + 16) * B + 4);
            w0 = *reinterpret_cast<const float4*>(Wptr + k0 + 16);
            w1 = *reinterpret_cast<const float4*>(Wptr + k0 + 16 + 4);
        }
        const float* Asp = As[p];
        const float* Wsp = Ws[p];
        #pragma unroll
        for (int k = 0; k < 16; k++) {
            float2 ap[4];
            #pragma unroll
            for (int mi = 0; mi < 4; mi++)
                ap[mi] = *reinterpret_cast<const float2*>(Asp + k * 132 + 2 * ty + 32 * mi);
            ulonglong2 bn0 = *reinterpret_cast<const ulonglong2*>(Wsp + k * 132 + tx * 8);
            ulonglong2 bn1 = *reinterpret_cast<const ulonglong2*>(Wsp + k * 132 + tx * 8 + 4);
            ull bp[4] = {bn0.x, bn0.y, bn1.x, bn1.y};
            #pragma unroll
            for (int mi = 0; mi < 4; mi++) {
                ull ax = pack2(ap[mi].x, ap[mi].x);
                ull ay = pack2(ap[mi].y, ap[mi].y);
                #pragma unroll
                for (int np = 0; np < 4; np++) {
                    fma2(acc[2 * mi][np],     ax, bp[np]);
                    fma2(acc[2 * mi + 1][np], ay, bp[np]);
                }
            }
        }
        if (more) {
            int q = p ^ 1;
            *reinterpret_cast<float4*>(&As[q][lk * 132 + lb])     = h0;
            *reinterpret_cast<float4*>(&As[q][lk * 132 + lb + 4]) = h1;
            Ws[q][(lq + 0) * 132 + lm] = w0.x; Ws[q][(lq + 1) * 132 + lm] = w0.y;
            Ws[q][(lq + 2) * 132 + lm] = w0.z; Ws[q][(lq + 3) * 132 + lm] = w0.w;
            Ws[q][(lq + 4) * 132 + lm] = w1.x; Ws[q][(lq + 5) * 132 + lm] = w1.y;
            Ws[q][(lq + 6) * 132 + lm] = w1.z; Ws[q][(lq + 7) * 132 + lm] = w1.w;
            __syncthreads();
            p = q;
        }
    }
    #pragma unroll
    for (int r = 0; r < 8; r++) {
        int m = m0 + 2 * ty + 32 * (r >> 1) + (r & 1);
        float cv[8];
        #pragma unroll
        for (int np = 0; np < 4; np++) {
            float2 pv = unpack2(acc[r][np]);
            float v0 = pv.x + bias[n0 + tx * 8 + 2 * np];
            float v1 = pv.y + bias[n0 + tx * 8 + 2 * np + 1];
            if (act == 1) { v0 = fmaxf(v0, 0.0f); v1 = fmaxf(v1, 0.0f); }
            cv[2 * np] = v0; cv[2 * np + 1] = v1;
        }
        float4 s0 = make_float4(cv[0], cv[1], cv[2], cv[3]);
        float4 s1 = make_float4(cv[4], cv[5], cv[6], cv[7]);
        *reinterpret_cast<float4*>(C + (size_t)m * ldc + n0 + tx * 8)     = s0;
        *reinterpret_cast<float4*>(C + (size_t)m * ldc + n0 + tx * 8 + 4) = s1;
    }
}

// ---------------- persistent GRU scan (exact R10 structure) ----------------
extern __shared__ float smem_dyn[];

__global__ void __launch_bounds__(SCAN_THREADS, 1)
k_gru_scan(const float* __restrict__ giT,  // [T][G][B]
           const float* __restrict__ Wh,   // [G, H]
           const float* __restrict__ bh,   // [G]
           float* __restrict__ hT)         // [(T+1), H, B]
{
    float* ws  = smem_dyn;                     // [512][12] : ws[k*12 + c], c = g*4+jj
    float* red = ws + 512 * 12;                // [16][12][128]
    float* sbh = red + SCAN_WARPS * 12 * 128;  // [12]
    const int tid  = threadIdx.x;
    const int warp = tid >> 5;
    const int lane = tid & 31;
    const int j0   = blockIdx.x * 4;

    for (int i = tid; i < 12 * 512; i += SCAN_THREADS) {
        int c = i >> 9, k = i & 511;
        ws[k * 12 + c] = Wh[((size_t)((c >> 2) * H + j0 + (c & 3))) * H + k];
    }
    if (tid < 12) sbh[tid] = bh[(tid >> 2) * H + j0 + (tid & 3)];
    __syncthreads();

    const int k0 = warp * 32;
    const int bbase = lane * 4;
    const int gjj = tid >> 7;       // gate-phase j
    const int gb  = tid & 127;      // gate-phase b
    const float bias_r = sbh[gjj];
    const float bias_z = sbh[4 + gjj];
    const float bias_n = sbh[8 + gjj];

    for (int t = 0; t < T; t++) {
        const float* hprev = hT + (size_t)t * (H * B);

        // prefetch gate-phase operands (coalesced; completes under the k-loop)
        size_t gibase = ((size_t)t * G + j0 + gjj) * B + gb;
        float ir  = giT[gibase];
        float iz  = giT[gibase + (size_t)H * B];
        float inn = giT[gibase + (size_t)2 * H * B];
        float hp  = hprev[(size_t)(j0 + gjj) * B + gb];

        ull acc[4][6];
        #pragma unroll
        for (int i = 0; i < 4; i++)
            #pragma unroll
            for (int cp = 0; cp < 6; cp++) acc[i][cp] = 0ull;

        #pragma unroll 4
        for (int kk = 0; kk < 32; kk++) {
            int k = k0 + kk;
            float4 hv = *reinterpret_cast<const float4*>(hprev + (size_t)k * B + bbase);
            ull h2[4];
            h2[0] = pack2(hv.x, hv.x);
            h2[1] = pack2(hv.y, hv.y);
            h2[2] = pack2(hv.z, hv.z);
            h2[3] = pack2(hv.w, hv.w);
            const float* wrow = ws + k * 12;
            #pragma unroll
            for (int cp = 0; cp < 6; cp++) {
                ull w2 = *reinterpret_cast<const ull*>(wrow + cp * 2);
                #pragma unroll
                for (int i = 0; i < 4; i++) fma2(acc[i][cp], h2[i], w2);
            }
        }

        #pragma unroll
        for (int cp = 0; cp < 6; cp++) {
            float2 v0 = unpack2(acc[0][cp]);
            float2 v1 = unpack2(acc[1][cp]);
            float2 v2 = unpack2(acc[2][cp]);
            float2 v3 = unpack2(acc[3][cp]);
            float4 a  = make_float4(v0.x, v1.x, v2.x, v3.x);
            float4 b4 = make_float4(v0.y, v1.y, v2.y, v3.y);
            *reinterpret_cast<float4*>(red + ((size_t)(warp * 12 + 2 * cp)) * B + bbase)     = a;
            *reinterpret_cast<float4*>(red + ((size_t)(warp * 12 + 2 * cp + 1)) * B + bbase) = b4;
        }
        __syncthreads();

        // gate phase: 512 outputs, one per thread
        {
            float gr = 0.f, gz = 0.f, gn = 0.f;
            #pragma unroll
            for (int w = 0; w < SCAN_WARPS; w++) {
                gr += red[(w * 12 + 0 + gjj) * B + gb];
                gz += red[(w * 12 + 4 + gjj) * B + gb];
                gn += red[(w * 12 + 8 + gjj) * B + gb];
            }
            float r = fsigmoid_(ir + gr + bias_r);
            float u = fsigmoid_(iz + gz + bias_z);
            float n = ftanh_(inn + r * (gn + bias_n));
            hT[((size_t)(t + 1) * H + j0 + gjj) * B + gb] = (1.0f - u) * n + u * hp;
        }

        grid_barrier();
    }
}

// ---------------- encoder output: zm, zs, z, planar flow + kld_z partials ----------------
__global__ void k_flow_enc(const float* __restrict__ head,
                           const float* __restrict__ eps_enc,
                           const float* __restrict__ w_flow,
                           const float* __restrict__ b_flow,
                           const float* __restrict__ u_flow,
                           float* __restrict__ out,
                           float* __restrict__ z_all,
                           double* __restrict__ pz) {
    __shared__ float red[4][64];
    __shared__ double dred[256];
    int rl = threadIdx.x >> 6;
    int j = threadIdx.x & 63;
    int row = blockIdx.x * 4 + rl;       // t*B + b
    int t = row >> 7;
    int b = row & 127;

    float zm = sigmoidf_(head[row * 128 + j]);
    float zs = softplusf_(head[row * 128 + 64 + j]);
    float eps = eps_enc[b * (T * Z) + t * Z + j];
    float z = eps * zs + zm;

    #pragma unroll
    for (int k = 0; k < KF; k++) {
        red[rl][j] = z * w_flow[(t * KF + k) * Z + j];
        __syncthreads();
        #pragma unroll
        for (int s = 32; s > 0; s >>= 1) {
            if (j < s) red[rl][j] += red[rl][j + s];
            __syncthreads();
        }
        float sv = red[rl][0] + b_flow[t * KF + k];
        __syncthreads();
        z += u_flow[(t * KF + k) * Z + j] * tanhf(sv);
    }

    int o = (b * T + t) * Z + j;
    out[2 + o]         = z;
    out[2 + S + o]     = zm;
    out[2 + 2 * S + o] = zs;
    z_all[row * Z + j] = z;

    // kld_z partial: 1 + zs - zm^2 - exp(zs) (float exp, double accumulate)
    float ez = expf(zs);
    dred[threadIdx.x] = 1.0 + (double)zs - (double)zm * (double)zm - (double)ez;
    __syncthreads();
    for (int s = 128; s > 0; s >>= 1) {
        if (threadIdx.x < s) dred[threadIdx.x] += dred[threadIdx.x + s];
        __syncthreads();
    }
    if (threadIdx.x == 0) pz[blockIdx.x] = dred[0];
}

// ---------------- decoder output + nll/kld_x partials ----------------
__global__ void k_dec_out(const float* __restrict__ head,
                          const float* __restrict__ eps_dec,
                          const float* __restrict__ x,
                          float* __restrict__ out,
                          double* __restrict__ pn,
                          double* __restrict__ px) {
    __shared__ double sn[256];
    __shared__ double sk[256];
    int i = blockIdx.x * blockDim.x + threadIdx.x;
    int row = i >> 6;
    int j = i & 63;
    int t = row >> 7;
    int b = row & 127;
    float xm = sigmoidf_(head[row * 128 + j]);
    float xs = softplusf_(head[row * 128 + 64 + j]);
    int src = b * (T * Xd) + t * Xd + j;
    float eps = eps_dec[src];
    float xo = eps * xs + xm;
    int o = (b * T + t) * Xd + j;
    out[2 + 3 * S + o] = xo;
    out[2 + 4 * S + o] = xm;
    out[2 + 5 * S + o] = xs;

    float xv = x[src];
    float dq = (xv - xm) * expf(-0.5f * xs);
    float ex = expf(xs);
    sn[threadIdx.x] = (double)xs + (double)dq * (double)dq;
    sk[threadIdx.x] = 1.0 + (double)xs - (double)xm * (double)xm - (double)ex;
    __syncthreads();
    for (int s = 128; s > 0; s >>= 1) {
        if (threadIdx.x < s) {
            sn[threadIdx.x] += sn[threadIdx.x + s];
            sk[threadIdx.x] += sk[threadIdx.x + s];
        }
        __syncthreads();
    }
    if (threadIdx.x == 0) {
        pn[blockIdx.x] = sn[0];
        px[blockIdx.x] = sk[0];
    }
}

// ---------------- final deterministic reduction ----------------
__global__ void k_reduce_final(const double* __restrict__ pz,
                               const double* __restrict__ pn,
                               const double* __restrict__ px,
                               float* __restrict__ out) {
    __shared__ double sn[256];
    __shared__ double sk[256];
    double an = 0.0, ak = 0.0;
    for (int i = threadIdx.x; i < 2048; i += 256) {
        an += pn[i];
        ak += pz[i] + px[i];
    }
    sn[threadIdx.x] = an;
    sk[threadIdx.x] = ak;
    __syncthreads();
    for (int s = 128; s > 0; s >>= 1) {
        if (threadIdx.x < s) {
            sn[threadIdx.x] += sn[threadIdx.x + s];
            sk[threadIdx.x] += sk[threadIdx.x + s];
        }
        __syncthreads();
    }
    if (threadIdx.x == 0) {
        out[0] = (float)(0.5 * sn[0]);
        out[1] = (float)(-0.5 * sk[0]);
    }
}

// ---------------- launch ----------------
extern "C" void kernel_launch(void* const* d_in, const int* in_sizes, int n_in,
                              void* d_out, int out_size) {
    const float* x        = (const float*)d_in[0];
    const float* eps_enc  = (const float*)d_in[1];
    const float* eps_dec  = (const float*)d_in[2];
    const float* Wi_enc   = (const float*)d_in[3];
    const float* Wh_enc   = (const float*)d_in[4];
    const float* bi_enc   = (const float*)d_in[5];
    const float* bh_enc   = (const float*)d_in[6];
    const float* Wphi_enc = (const float*)d_in[7];
    const float* bphi_enc = (const float*)d_in[8];
    const float* W_zmean  = (const float*)d_in[9];
    const float* b_zmean  = (const float*)d_in[10];
    const float* W_zstd   = (const float*)d_in[11];
    const float* b_zstd   = (const float*)d_in[12];
    const float* w_flow   = (const float*)d_in[13];
    const float* b_flow   = (const float*)d_in[14];
    const float* u_flow   = (const float*)d_in[15];
    const float* Wi_dec   = (const float*)d_in[16];
    const float* Wh_dec   = (const float*)d_in[17];
    const float* bi_dec   = (const float*)d_in[18];
    const float* bh_dec   = (const float*)d_in[19];
    const float* Wphi_dec = (const float*)d_in[20];
    const float* bphi_dec = (const float*)d_in[21];
    const float* W_xmean  = (const float*)d_in[22];
    const float* b_xmean  = (const float*)d_in[23];
    const float* W_xstd   = (const float*)d_in[24];
    const float* b_xstd   = (const float*)d_in[25];
    float* out = (float*)d_out;

    float *p_xT, *p_gi, *p_h, *p_phi, *p_head, *p_z;
    float *p_WhZ, *p_bhZ, *p_WhX, *p_bhX;
    double *p_pz, *p_pn, *p_px;
    cudaGetSymbolAddress((void**)&p_xT,   g_xT);
    cudaGetSymbolAddress((void**)&p_gi,   g_gi);
    cudaGetSymbolAddress((void**)&p_h,    g_h);
    cudaGetSymbolAddress((void**)&p_phi,  g_phi);
    cudaGetSymbolAddress((void**)&p_head, g_head);
    cudaGetSymbolAddress((void**)&p_z,    g_z);
    cudaGetSymbolAddress((void**)&p_WhZ,  g_WheadZ);
    cudaGetSymbolAddress((void**)&p_bhZ,  g_bheadZ);
    cudaGetSymbolAddress((void**)&p_WhX,  g_WheadX);
    cudaGetSymbolAddress((void**)&p_bhX,  g_bheadX);
    cudaGetSymbolAddress((void**)&p_pz,   g_pz);
    cudaGetSymbolAddress((void**)&p_pn,   g_pn);
    cudaGetSymbolAddress((void**)&p_px,   g_px);

    cudaFuncSetAttribute(k_gru_scan, cudaFuncAttributeMaxDynamicSharedMemorySize, SCAN_SMEM);

    // 0) fused prep: transpose x, zero h0, pack head weights
    k_prep<<<(721152 + 255) / 256, 256>>>(x, W_zmean, b_zmean, W_zstd, b_zstd,
                                          W_xmean, b_xmean, W_xstd, b_xstd,
                                          p_xT, p_h, p_WhZ, p_bhZ, p_WhX, p_bhX);

    // 1) gi_enc = xT @ Wi_enc.T + bi_enc -> transposed [t][col][b]
    {
        dim3 grid(BT / 128, G / 128);
        k_gemm<<<grid, 256>>>(p_xT, Xd, Wi_enc, Xd, bi_enc, p_gi, G, Xd, 0, 1);
    }
    // 2) encoder GRU scan (persistent)
    k_gru_scan<<<NBLK, SCAN_THREADS, SCAN_SMEM>>>(p_gi, Wh_enc, bh_enc, p_h);

    // 3) phi_enc = relu(h_all @ Wphi_enc[:, :H].T + b)
    {
        dim3 grid(BT / 128, D / 128);
        k_gemm_ht<<<grid, 256>>>(p_h, Wphi_enc, H + Z, bphi_enc, p_phi, D, H, 1);
    }
    // 4) z heads (fused N=128 GEMM)
    {
        dim3 grid(BT / 128, 1);
        k_gemm<<<grid, 256>>>(p_phi, D, p_WhZ, D, p_bhZ, p_head, 128, D, 0, 0);
    }
    // 5) flow + z outputs + kld_z partials
    k_flow_enc<<<BT / 4, 256>>>(p_head, eps_enc, w_flow, b_flow, u_flow, out, p_z, p_pz);

    // 6) gi_dec = z_all @ Wi_dec.T + bi_dec -> transposed
    {
        dim3 grid(BT / 128, G / 128);
        k_gemm<<<grid, 256>>>(p_z, Z, Wi_dec, Z, bi_dec, p_gi, G, Z, 0, 1);
    }
    // 7) decoder GRU scan (h slab 0 still zero)
    k_gru_scan<<<NBLK, SCAN_THREADS, SCAN_SMEM>>>(p_gi, Wh_dec, bh_dec, p_h);

    // 8) phi_dec
    {
        dim3 grid(BT / 128, D / 128);
        k_gemm_ht<<<grid, 256>>>(p_h, Wphi_dec, H, bphi_dec, p_phi, D, H, 1);
    }
    // 9) x heads (fused)
    {
        dim3 grid(BT / 128, 1);
        k_gemm<<<grid, 256>>>(p_phi, D, p_WhX, D, p_bhX, p_head, 128, D, 0, 0);
    }
    // 10) decoder outputs + nll/kld_x partials
    k_dec_out<<<S / 256, 256>>>(p_head, eps_dec, x, out, p_pn, p_px);

    // 11) final reduction
    k_reduce_final<<<1, 256>>>(p_pz, p_pn, p_px, out);
}

// round 14
// speedup vs baseline: 1.1190x; 1.0126x over previous
#include <cuda_runtime.h>
#include <math.h>

// Problem dims
#define B   128
#define T   64
#define Xd  64
#define H   512
#define D   512
#define Z   64
#define KF  2
#define G   1536          // 3*H
#define BT  8192          // B*T
#define S   524288        // B*T*64
#define NBLK 128
#define SCAN_THREADS 512
#define SCAN_WARPS 16
#define SCAN_SMEM ((512*12 + SCAN_WARPS*12*128 + 16) * 4)

typedef unsigned long long ull;

// ---------------- scratch ----------------
__device__ float  g_xT[BT * Xd];           // x rearranged to [t*B+b][X]
__device__ float  g_gi[T * G * B];         // gi TRANSPOSED: [t][col][b]
__device__ float  g_h[(T + 1) * H * B];    // h TRANSPOSED: [t][k][b], slab 0 = zeros
__device__ float  g_phi[BT * D];
__device__ float  g_head[BT * 128];
__device__ float  g_z[BT * Z];
__device__ float  g_WheadZ[128 * 512];
__device__ float  g_bheadZ[128];
__device__ float  g_WheadX[128 * 512];
__device__ float  g_bheadX[128];
__device__ double g_pz[2048];              // kld_z partials (flow blocks)
__device__ double g_pn[2048];              // nll partials (dec_out blocks)
__device__ double g_px[2048];              // kld_x partials (dec_out blocks)
__device__ unsigned g_bar_count = 0;
__device__ unsigned g_bar_gen = 0;

// ---------------- helpers ----------------
__device__ __forceinline__ float sigmoidf_(float v) { return 1.0f / (1.0f + expf(-v)); }
__device__ __forceinline__ float softplusf_(float v) { return (v > 20.0f) ? v : log1pf(expf(v)); }
__device__ __forceinline__ float fsigmoid_(float v) { return 1.0f / (1.0f + __expf(-v)); }
__device__ __forceinline__ float ftanh_(float v) { return 1.0f - 2.0f / (__expf(2.0f * v) + 1.0f); }
__device__ __forceinline__ float fsoftplus_(float v) {
    return (v > 20.0f) ? v : __logf(1.0f + __expf(v));
}

__device__ __forceinline__ void fma2(ull &a, ull x, ull y) {
    asm("fma.rn.f32x2 %0, %1, %2, %0;" : "+l"(a) : "l"(x), "l"(y));
}
__device__ __forceinline__ ull pack2(float lo, float hi) {
    ull r;
    asm("mov.b64 %0, {%1, %2};" : "=l"(r) : "f"(lo), "f"(hi));
    return r;
}
__device__ __forceinline__ float2 unpack2(ull v) {
    float2 r;
    asm("mov.b64 {%0, %1}, %2;" : "=f"(r.x), "=f"(r.y) : "l"(v));
    return r;
}

// monotonic-counter grid barrier (no reset race); NBLK is a power of two
__device__ __forceinline__ void grid_barrier() {
    __threadfence();
    __syncthreads();
    if (threadIdx.x == 0) {
        volatile unsigned* vgen = &g_bar_gen;
        unsigned gen = *vgen;
        unsigned prev = atomicAdd(&g_bar_count, 1u);
        if ((prev & (NBLK - 1)) == (NBLK - 1)) {
            __threadfence();
            *vgen = gen + 1;
        } else {
            while (*vgen == gen) { }
            __threadfence();
        }
    }
    __syncthreads();
}

// ---------------- fused prep ----------------
__global__ void k_prep(const float* __restrict__ x,
                       const float* __restrict__ Wzm, const float* __restrict__ bzm,
                       const float* __restrict__ Wzs, const float* __restrict__ bzs,
                       const float* __restrict__ Wxm, const float* __restrict__ bxm,
                       const float* __restrict__ Wxs, const float* __restrict__ bxs,
                       float* __restrict__ xT, float* __restrict__ h0,
                       float* __restrict__ WhZ, float* __restrict__ bhZ,
                       float* __restrict__ WhX, float* __restrict__ bhX) {
    int i = blockIdx.x * blockDim.x + threadIdx.x;
    if (i < 524288) {
        int b = i >> 12;
        int r = i & 4095;
        int t = r >> 6;
        int xi = r & 63;
        xT[((t << 7) + b) * Xd + xi] = x[i];
    } else if (i < 589824) {
        h0[i - 524288] = 0.0f;
    } else if (i < 622592) {
        int q = i - 589824; WhZ[q] = Wzm[q];
    } else if (i < 655360) {
        int q = i - 622592; WhZ[32768 + q] = Wzs[q];
    } else if (i < 688128) {
        int q = i - 655360; WhX[q] = Wxm[q];
    } else if (i < 720896) {
        int q = i - 688128; WhX[32768 + q] = Wxs[q];
    } else if (i < 721152) {
        int q = i - 720896;  // 0..255
        if (q < 64)        bhZ[q] = bzm[q];
        else if (q < 128)  bhZ[q] = bzs[q - 64];
        else if (q < 192)  bhX[q - 128] = bxm[q - 128];
        else               bhX[q - 128] = bxs[q - 192];
    }
}

// ---------------- tiled GEMM 128x128, 256 threads, 8x8 per thread ----------------
// Ping-pong double-buffered, A reads as 2x LDS.128 (m = 4*ty + 64*mi + q).
__global__ void __launch_bounds__(256, 2)
k_gemm(const float* __restrict__ A, int lda,
       const float* __restrict__ W, int ldw,
       const float* __restrict__ bias,
       float* __restrict__ C, int ldc,
       int K, int act, int cmode) {
    __shared__ float As[2][16 * 132];
    __shared__ float Ws[2][16 * 132];
    const int m0 = blockIdx.x * 128;
    const int n0 = blockIdx.y * 128;
    const int tx = threadIdx.x >> 4;
    const int ty = threadIdx.x & 15;
    const int lm = threadIdx.x >> 1;
    const int lq = (threadIdx.x & 1) * 8;

    const float* Aptr = A + (size_t)(m0 + lm) * lda + lq;
    const float* Wptr = W + (size_t)(n0 + lm) * ldw + lq;

    ull acc[8][4];
    #pragma unroll
    for (int i = 0; i < 8; i++)
        #pragma unroll
        for (int j = 0; j < 4; j++) acc[i][j] = 0ull;

    {
        float4 a0 = *reinterpret_cast<const float4*>(Aptr);
        float4 a1 = *reinterpret_cast<const float4*>(Aptr + 4);
        float4 w0 = *reinterpret_cast<const float4*>(Wptr);
        float4 w1 = *reinterpret_cast<const float4*>(Wptr + 4);
        As[0][(lq + 0) * 132 + lm] = a0.x; As[0][(lq + 1) * 132 + lm] = a0.y;
        As[0][(lq + 2) * 132 + lm] = a0.z; As[0][(lq + 3) * 132 + lm] = a0.w;
        As[0][(lq + 4) * 132 + lm] = a1.x; As[0][(lq + 5) * 132 + lm] = a1.y;
        As[0][(lq + 6) * 132 + lm] = a1.z; As[0][(lq + 7) * 132 + lm] = a1.w;
        Ws[0][(lq + 0) * 132 + lm] = w0.x; Ws[0][(lq + 1) * 132 + lm] = w0.y;
        Ws[0][(lq + 2) * 132 + lm] = w0.z; Ws[0][(lq + 3) * 132 + lm] = w0.w;
        Ws[0][(lq + 4) * 132 + lm] = w1.x; Ws[0][(lq + 5) * 132 + lm] = w1.y;
        Ws[0][(lq + 6) * 132 + lm] = w1.z; Ws[0][(lq + 7) * 132 + lm] = w1.w;
    }
    __syncthreads();

    int p = 0;
    for (int k0 = 0; k0 < K; k0 += 16) {
        const bool more = (k0 + 16 < K);
        float4 a0, a1, w0, w1;
        if (more) {
            a0 = *reinterpret_cast<const float4*>(Aptr + k0 + 16);
            a1 = *reinterpret_cast<const float4*>(Aptr + k0 + 16 + 4);
            w0 = *reinterpret_cast<const float4*>(Wptr + k0 + 16);
            w1 = *reinterpret_cast<const float4*>(Wptr + k0 + 16 + 4);
        }
        const float* Asp = As[p];
        const float* Wsp = Ws[p];
        #pragma unroll
        for (int k = 0; k < 16; k++) {
            // A: 2x LDS.128, m = 4*ty + 64*mi + q (conflict-free)
            float4 ap[2];
            #pragma unroll
            for (int mi = 0; mi < 2; mi++)
                ap[mi] = *reinterpret_cast<const float4*>(Asp + k * 132 + 4 * ty + 64 * mi);
            ulonglong2 bn0 = *reinterpret_cast<const ulonglong2*>(Wsp + k * 132 + tx * 8);
            ulonglong2 bn1 = *reinterpret_cast<const ulonglong2*>(Wsp + k * 132 + tx * 8 + 4);
            ull bp[4] = {bn0.x, bn0.y, bn1.x, bn1.y};
            #pragma unroll
            for (int mi = 0; mi < 2; mi++) {
                float aval[4] = {ap[mi].x, ap[mi].y, ap[mi].z, ap[mi].w};
                #pragma unroll
                for (int q = 0; q < 4; q++) {
                    ull ax = pack2(aval[q], aval[q]);
                    #pragma unroll
                    for (int np = 0; np < 4; np++) fma2(acc[4 * mi + q][np], ax, bp[np]);
                }
            }
        }
        if (more) {
            int q = p ^ 1;
            As[q][(lq + 0) * 132 + lm] = a0.x; As[q][(lq + 1) * 132 + lm] = a0.y;
            As[q][(lq + 2) * 132 + lm] = a0.z; As[q][(lq + 3) * 132 + lm] = a0.w;
            As[q][(lq + 4) * 132 + lm] = a1.x; As[q][(lq + 5) * 132 + lm] = a1.y;
            As[q][(lq + 6) * 132 + lm] = a1.z; As[q][(lq + 7) * 132 + lm] = a1.w;
            Ws[q][(lq + 0) * 132 + lm] = w0.x; Ws[q][(lq + 1) * 132 + lm] = w0.y;
            Ws[q][(lq + 2) * 132 + lm] = w0.z; Ws[q][(lq + 3) * 132 + lm] = w0.w;
            Ws[q][(lq + 4) * 132 + lm] = w1.x; Ws[q][(lq + 5) * 132 + lm] = w1.y;
            Ws[q][(lq + 6) * 132 + lm] = w1.z; Ws[q][(lq + 7) * 132 + lm] = w1.w;
            __syncthreads();
            p = q;
        }
    }

    float cv[8][8];   // cv[4*mi+q][n], m = 4*ty + 64*mi + q
    #pragma unroll
    for (int r = 0; r < 8; r++) {
        #pragma unroll
        for (int np = 0; np < 4; np++) {
            float2 pv = unpack2(acc[r][np]);
            float v0 = pv.x + bias[n0 + tx * 8 + 2 * np];
            float v1 = pv.y + bias[n0 + tx * 8 + 2 * np + 1];
            if (act == 1) { v0 = fmaxf(v0, 0.0f); v1 = fmaxf(v1, 0.0f); }
            cv[r][2 * np] = v0; cv[r][2 * np + 1] = v1;
        }
    }
    if (cmode == 0) {
        #pragma unroll
        for (int r = 0; r < 8; r++) {
            int m = m0 + 4 * ty + 64 * (r >> 2) + (r & 3);
            float4 s0 = make_float4(cv[r][0], cv[r][1], cv[r][2], cv[r][3]);
            float4 s1 = make_float4(cv[r][4], cv[r][5], cv[r][6], cv[r][7]);
            *reinterpret_cast<float4*>(C + (size_t)m * ldc + n0 + tx * 8)     = s0;
            *reinterpret_cast<float4*>(C + (size_t)m * ldc + n0 + tx * 8 + 4) = s1;
        }
    } else {
        const int t = blockIdx.x;          // m-tile == one full B
        #pragma unroll
        for (int j = 0; j < 8; j++) {
            int n = n0 + tx * 8 + j;
            size_t base = ((size_t)t * ldc + n) * B;
            #pragma unroll
            for (int mi = 0; mi < 2; mi++) {
                int m = 4 * ty + 64 * mi;
                *reinterpret_cast<float4*>(C + base + m) =
                    make_float4(cv[4 * mi][j], cv[4 * mi + 1][j],
                                cv[4 * mi + 2][j], cv[4 * mi + 3][j]);
            }
        }
    }
}

// ---------------- GEMM variant: A from transposed h [(t+1)][k][b], ping-pong ----------------
__global__ void __launch_bounds__(256, 2)
k_gemm_ht(const float* __restrict__ hT,
          const float* __restrict__ W, int ldw,
          const float* __restrict__ bias,
          float* __restrict__ C, int ldc,
          int K, int act) {
    __shared__ float As[2][16 * 132];
    __shared__ float Ws[2][16 * 132];
    const int m0 = blockIdx.x * 128;
    const int n0 = blockIdx.y * 128;
    const size_t slab = (size_t)(blockIdx.x + 1) * (H * B);
    const int tx = threadIdx.x >> 4;
    const int ty = threadIdx.x & 15;
    const int lm = threadIdx.x >> 1;
    const int lq = (threadIdx.x & 1) * 8;
    const int lk = threadIdx.x >> 4;
    const int lb = (threadIdx.x & 15) * 8;

    const float* Hptr = hT + slab + (size_t)lk * B + lb;
    const float* Wptr = W + (size_t)(n0 + lm) * ldw + lq;

    ull acc[8][4];
    #pragma unroll
    for (int i = 0; i < 8; i++)
        #pragma unroll
        for (int j = 0; j < 4; j++) acc[i][j] = 0ull;

    {
        float4 h0 = *reinterpret_cast<const float4*>(Hptr);
        float4 h1 = *reinterpret_cast<const float4*>(Hptr + 4);
        float4 w0 = *reinterpret_cast<const float4*>(Wptr);
        float4 w1 = *reinterpret_cast<const float4*>(Wptr + 4);
        *reinterpret_cast<float4*>(&As[0][lk * 132 + lb])     = h0;
        *reinterpret_cast<float4*>(&As[0][lk * 132 + lb + 4]) = h1;
        Ws[0][(lq + 0) * 132 + lm] = w0.x; Ws[0][(lq + 1) * 132 + lm] = w0.y;
        Ws[0][(lq + 2) * 132 + lm] = w0.z; Ws[0][(lq + 3) * 132 + lm] = w0.w;
        Ws[0][(lq + 4) * 132 + lm] = w1.x; Ws[0][(lq + 5) * 132 + lm] = w1.y;
        Ws[0][(lq + 6) * 132 + lm] = w1.z; Ws[0][(lq + 7) * 132 + lm] = w1.w;
    }
    __syncthreads();

    int p = 0;
    for (int k0 = 0; k0 < K; k0 += 16) {
        const bool more = (k0 + 16 < K);
        float4 h0, h1, w0, w1;
        if (more) {
            h0 = *reinterpret_cast<const float4*>(Hptr + (size_t)(k0 + 16) * B);
            h1 = *reinterpret_cast<const float4*>(Hptr + (size_t)(k0 + 16) * B + 4);
            w0 = *reinterpret_cast<const float4*>(Wptr + k0 + 16);
            w1 = *reinterpret_cast<const float4*>(Wptr + k0 + 16 + 4);
        }
        const float* Asp = As[p];
        const float* Wsp = Ws[p];
        #pragma unroll
        for (int k = 0; k < 16; k++) {
            float4 ap[2];
            #pragma unroll
            for (int mi = 0; mi < 2; mi++)
                ap[mi] = *reinterpret_cast<const float4*>(Asp + k * 132 + 4 * ty + 64 * mi);
            ulonglong2 bn0 = *reinterpret_cast<const ulonglong2*>(Wsp + k * 132 + tx * 8);
            ulonglong2 bn1 = *reinterpret_cast<const ulonglong2*>(Wsp + k * 132 + tx * 8 + 4);
            ull bp[4] = {bn0.x, bn0.y, bn1.x, bn1.y};
            #pragma unroll
            for (int mi = 0; mi < 2; mi++) {
                float aval[4] = {ap[mi].x, ap[mi].y, ap[mi].z, ap[mi].w};
                #pragma unroll
                for (int q = 0; q < 4; q++) {
                    ull ax = pack2(aval[q], aval[q]);
                    #pragma unroll
                    for (int np = 0; np < 4; np++) fma2(acc[4 * mi + q][np], ax, bp[np]);
                }
            }
        }
        if (more) {
            int q = p ^ 1;
            *reinterpret_cast<float4*>(&As[q][lk * 132 + lb])     = h0;
            *reinterpret_cast<float4*>(&As[q][lk * 132 + lb + 4]) = h1;
            Ws[q][(lq + 0) * 132 + lm] = w0.x; Ws[q][(lq + 1) * 132 + lm] = w0.y;
            Ws[q][(lq + 2) * 132 + lm] = w0.z; Ws[q][(lq + 3) * 132 + lm] = w0.w;
            Ws[q][(lq + 4) * 132 + lm] = w1.x; Ws[q][(lq + 5) * 132 + lm] = w1.y;
            Ws[q][(lq + 6) * 132 + lm] = w1.z; Ws[q][(lq + 7) * 132 + lm] = w1.w;
            __syncthreads();
            p = q;
        }
    }
    #pragma unroll
    for (int r = 0; r < 8; r++) {
        int m = m0 + 4 * ty + 64 * (r >> 2) + (r & 3);
        float cv[8];
        #pragma unroll
        for (int np = 0; np < 4; np++) {
            float2 pv = unpack2(acc[r][np]);
            float v0 = pv.x + bias[n0 + tx * 8 + 2 * np];
            float v1 = pv.y + bias[n0 + tx * 8 + 2 * np + 1];
            if (act == 1) { v0 = fmaxf(v0, 0.0f); v1 = fmaxf(v1, 0.0f); }
            cv[2 * np] = v0; cv[2 * np + 1] = v1;
        }
        float4 s0 = make_float4(cv[0], cv[1], cv[2], cv[3]);
        float4 s1 = make_float4(cv[4], cv[5], cv[6], cv[7]);
        *reinterpret_cast<float4*>(C + (size_t)m * ldc + n0 + tx * 8)     = s0;
        *reinterpret_cast<float4*>(C + (size_t)m * ldc + n0 + tx * 8 + 4) = s1;
    }
}

// ---------------- persistent GRU scan (exact R10 structure) ----------------
extern __shared__ float smem_dyn[];

__global__ void __launch_bounds__(SCAN_THREADS, 1)
k_gru_scan(const float* __restrict__ giT,  // [T][G][B]
           const float* __restrict__ Wh,   // [G, H]
           const float* __restrict__ bh,   // [G]
           float* __restrict__ hT)         // [(T+1), H, B]
{
    float* ws  = smem_dyn;                     // [512][12] : ws[k*12 + c], c = g*4+jj
    float* red = ws + 512 * 12;                // [16][12][128]
    float* sbh = red + SCAN_WARPS * 12 * 128;  // [12]
    const int tid  = threadIdx.x;
    const int warp = tid >> 5;
    const int lane = tid & 31;
    const int j0   = blockIdx.x * 4;

    for (int i = tid; i < 12 * 512; i += SCAN_THREADS) {
        int c = i >> 9, k = i & 511;
        ws[k * 12 + c] = Wh[((size_t)((c >> 2) * H + j0 + (c & 3))) * H + k];
    }
    if (tid < 12) sbh[tid] = bh[(tid >> 2) * H + j0 + (tid & 3)];
    __syncthreads();

    const int k0 = warp * 32;
    const int bbase = lane * 4;
    const int gjj = tid >> 7;       // gate-phase j
    const int gb  = tid & 127;      // gate-phase b
    const float bias_r = sbh[gjj];
    const float bias_z = sbh[4 + gjj];
    const float bias_n = sbh[8 + gjj];

    for (int t = 0; t < T; t++) {
        const float* hprev = hT + (size_t)t * (H * B);

        // prefetch gate-phase operands (coalesced; completes under the k-loop)
        size_t gibase = ((size_t)t * G + j0 + gjj) * B + gb;
        float ir  = giT[gibase];
        float iz  = giT[gibase + (size_t)H * B];
        float inn = giT[gibase + (size_t)2 * H * B];
        float hp  = hprev[(size_t)(j0 + gjj) * B + gb];

        ull acc[4][6];
        #pragma unroll
        for (int i = 0; i < 4; i++)
            #pragma unroll
            for (int cp = 0; cp < 6; cp++) acc[i][cp] = 0ull;

        #pragma unroll 4
        for (int kk = 0; kk < 32; kk++) {
            int k = k0 + kk;
            float4 hv = *reinterpret_cast<const float4*>(hprev + (size_t)k * B + bbase);
            ull h2[4];
            h2[0] = pack2(hv.x, hv.x);
            h2[1] = pack2(hv.y, hv.y);
            h2[2] = pack2(hv.z, hv.z);
            h2[3] = pack2(hv.w, hv.w);
            const float* wrow = ws + k * 12;
            #pragma unroll
            for (int cp = 0; cp < 6; cp++) {
                ull w2 = *reinterpret_cast<const ull*>(wrow + cp * 2);
                #pragma unroll
                for (int i = 0; i < 4; i++) fma2(acc[i][cp], h2[i], w2);
            }
        }

        #pragma unroll
        for (int cp = 0; cp < 6; cp++) {
            float2 v0 = unpack2(acc[0][cp]);
            float2 v1 = unpack2(acc[1][cp]);
            float2 v2 = unpack2(acc[2][cp]);
            float2 v3 = unpack2(acc[3][cp]);
            float4 a  = make_float4(v0.x, v1.x, v2.x, v3.x);
            float4 b4 = make_float4(v0.y, v1.y, v2.y, v3.y);
            *reinterpret_cast<float4*>(red + ((size_t)(warp * 12 + 2 * cp)) * B + bbase)     = a;
            *reinterpret_cast<float4*>(red + ((size_t)(warp * 12 + 2 * cp + 1)) * B + bbase) = b4;
        }
        __syncthreads();

        // gate phase: 512 outputs, one per thread
        {
            float gr = 0.f, gz = 0.f, gn = 0.f;
            #pragma unroll
            for (int w = 0; w < SCAN_WARPS; w++) {
                gr += red[(w * 12 + 0 + gjj) * B + gb];
                gz += red[(w * 12 + 4 + gjj) * B + gb];
                gn += red[(w * 12 + 8 + gjj) * B + gb];
            }
            float r = fsigmoid_(ir + gr + bias_r);
            float u = fsigmoid_(iz + gz + bias_z);
            float n = ftanh_(inn + r * (gn + bias_n));
            hT[((size_t)(t + 1) * H + j0 + gjj) * B + gb] = (1.0f - u) * n + u * hp;
        }

        grid_barrier();
    }
}

// ---------------- encoder output: zm, zs, z, planar flow + kld_z partials ----------------
__global__ void k_flow_enc(const float* __restrict__ head,
                           const float* __restrict__ eps_enc,
                           const float* __restrict__ w_flow,
                           const float* __restrict__ b_flow,
                           const float* __restrict__ u_flow,
                           float* __restrict__ out,
                           float* __restrict__ z_all,
                           double* __restrict__ pz) {
    __shared__ float red[4][64];
    __shared__ double dred[256];
    int rl = threadIdx.x >> 6;
    int j = threadIdx.x & 63;
    int row = blockIdx.x * 4 + rl;       // t*B + b
    int t = row >> 7;
    int b = row & 127;

    float zm = fsigmoid_(head[row * 128 + j]);
    float zs = fsoftplus_(head[row * 128 + 64 + j]);
    float eps = eps_enc[b * (T * Z) + t * Z + j];
    float z = eps * zs + zm;

    #pragma unroll
    for (int k = 0; k < KF; k++) {
        red[rl][j] = z * w_flow[(t * KF + k) * Z + j];
        __syncthreads();
        #pragma unroll
        for (int s = 32; s > 0; s >>= 1) {
            if (j < s) red[rl][j] += red[rl][j + s];
            __syncthreads();
        }
        float sv = red[rl][0] + b_flow[t * KF + k];
        __syncthreads();
        z += u_flow[(t * KF + k) * Z + j] * ftanh_(sv);
    }

    int o = (b * T + t) * Z + j;
    out[2 + o]         = z;
    out[2 + S + o]     = zm;
    out[2 + 2 * S + o] = zs;
    z_all[row * Z + j] = z;

    // kld_z partial: 1 + zs - zm^2 - exp(zs) (fast exp, double accumulate)
    float ez = __expf(zs);
    dred[threadIdx.x] = 1.0 + (double)zs - (double)zm * (double)zm - (double)ez;
    __syncthreads();
    for (int s = 128; s > 0; s >>= 1) {
        if (threadIdx.x < s) dred[threadIdx.x] += dred[threadIdx.x + s];
        __syncthreads();
    }
    if (threadIdx.x == 0) pz[blockIdx.x] = dred[0];
}

// ---------------- decoder output + nll/kld_x partials ----------------
__global__ void k_dec_out(const float* __restrict__ head,
                          const float* __restrict__ eps_dec,
                          const float* __restrict__ x,
                          float* __restrict__ out,
                          double* __restrict__ pn,
                          double* __restrict__ px) {
    __shared__ double sn[256];
    __shared__ double sk[256];
    int i = blockIdx.x * blockDim.x + threadIdx.x;
    int row = i >> 6;
    int j = i & 63;
    int t = row >> 7;
    int b = row & 127;
    float xm = fsigmoid_(head[row * 128 + j]);
    float xs = fsoftplus_(head[row * 128 + 64 + j]);
    int src = b * (T * Xd) + t * Xd + j;
    float eps = eps_dec[src];
    float xo = eps * xs + xm;
    int o = (b * T + t) * Xd + j;
    out[2 + 3 * S + o] = xo;
    out[2 + 4 * S + o] = xm;
    out[2 + 5 * S + o] = xs;

    float xv = x[src];
    float dq = (xv - xm) * __expf(-0.5f * xs);
    float ex = __expf(xs);
    sn[threadIdx.x] = (double)xs + (double)dq * (double)dq;
    sk[threadIdx.x] = 1.0 + (double)xs - (double)xm * (double)xm - (double)ex;
    __syncthreads();
    for (int s = 128; s > 0; s >>= 1) {
        if (threadIdx.x < s) {
            sn[threadIdx.x] += sn[threadIdx.x + s];
            sk[threadIdx.x] += sk[threadIdx.x + s];
        }
        __syncthreads();
    }
    if (threadIdx.x == 0) {
        pn[blockIdx.x] = sn[0];
        px[blockIdx.x] = sk[0];
    }
}

// ---------------- final deterministic reduction ----------------
__global__ void k_reduce_final(const double* __restrict__ pz,
                               const double* __restrict__ pn,
                               const double* __restrict__ px,
                               float* __restrict__ out) {
    __shared__ double sn[256];
    __shared__ double sk[256];
    double an = 0.0, ak = 0.0;
    for (int i = threadIdx.x; i < 2048; i += 256) {
        an += pn[i];
        ak += pz[i] + px[i];
    }
    sn[threadIdx.x] = an;
    sk[threadIdx.x] = ak;
    __syncthreads();
    for (int s = 128; s > 0; s >>= 1) {
        if (threadIdx.x < s) {
            sn[threadIdx.x] += sn[threadIdx.x + s];
            sk[threadIdx.x] += sk[threadIdx.x + s];
        }
        __syncthreads();
    }
    if (threadIdx.x == 0) {
        out[0] = (float)(0.5 * sn[0]);
        out[1] = (float)(-0.5 * sk[0]);
    }
}

// ---------------- launch ----------------
extern "C" void kernel_launch(void* const* d_in, const int* in_sizes, int n_in,
                              void* d_out, int out_size) {
    const float* x        = (const float*)d_in[0];
    const float* eps_enc  = (const float*)d_in[1];
    const float* eps_dec  = (const float*)d_in[2];
    const float* Wi_enc   = (const float*)d_in[3];
    const float* Wh_enc   = (const float*)d_in[4];
    const float* bi_enc   = (const float*)d_in[5];
    const float* bh_enc   = (const float*)d_in[6];
    const float* Wphi_enc = (const float*)d_in[7];
    const float* bphi_enc = (const float*)d_in[8];
    const float* W_zmean  = (const float*)d_in[9];
    const float* b_zmean  = (const float*)d_in[10];
    const float* W_zstd   = (const float*)d_in[11];
    const float* b_zstd   = (const float*)d_in[12];
    const float* w_flow   = (const float*)d_in[13];
    const float* b_flow   = (const float*)d_in[14];
    const float* u_flow   = (const float*)d_in[15];
    const float* Wi_dec   = (const float*)d_in[16];
    const float* Wh_dec   = (const float*)d_in[17];
    const float* bi_dec   = (const float*)d_in[18];
    const float* bh_dec   = (const float*)d_in[19];
    const float* Wphi_dec = (const float*)d_in[20];
    const float* bphi_dec = (const float*)d_in[21];
    const float* W_xmean  = (const float*)d_in[22];
    const float* b_xmean  = (const float*)d_in[23];
    const float* W_xstd   = (const float*)d_in[24];
    const float* b_xstd   = (const float*)d_in[25];
    float* out = (float*)d_out;

    float *p_xT, *p_gi, *p_h, *p_phi, *p_head, *p_z;
    float *p_WhZ, *p_bhZ, *p_WhX, *p_bhX;
    double *p_pz, *p_pn, *p_px;
    cudaGetSymbolAddress((void**)&p_xT,   g_xT);
    cudaGetSymbolAddress((void**)&p_gi,   g_gi);
    cudaGetSymbolAddress((void**)&p_h,    g_h);
    cudaGetSymbolAddress((void**)&p_phi,  g_phi);
    cudaGetSymbolAddress((void**)&p_head, g_head);
    cudaGetSymbolAddress((void**)&p_z,    g_z);
    cudaGetSymbolAddress((void**)&p_WhZ,  g_WheadZ);
    cudaGetSymbolAddress((void**)&p_bhZ,  g_bheadZ);
    cudaGetSymbolAddress((void**)&p_WhX,  g_WheadX);
    cudaGetSymbolAddress((void**)&p_bhX,  g_bheadX);
    cudaGetSymbolAddress((void**)&p_pz,   g_pz);
    cudaGetSymbolAddress((void**)&p_pn,   g_pn);
    cudaGetSymbolAddress((void**)&p_px,   g_px);

    cudaFuncSetAttribute(k_gru_scan, cudaFuncAttributeMaxDynamicSharedMemorySize, SCAN_SMEM);

    // 0) fused prep: transpose x, zero h0, pack head weights
    k_prep<<<(721152 + 255) / 256, 256>>>(x, W_zmean, b_zmean, W_zstd, b_zstd,
                                          W_xmean, b_xmean, W_xstd, b_xstd,
                                          p_xT, p_h, p_WhZ, p_bhZ, p_WhX, p_bhX);

    // 1) gi_enc = xT @ Wi_enc.T + bi_enc -> transposed [t][col][b]
    {
        dim3 grid(BT / 128, G / 128);
        k_gemm<<<grid, 256>>>(p_xT, Xd, Wi_enc, Xd, bi_enc, p_gi, G, Xd, 0, 1);
    }
    // 2) encoder GRU scan (persistent)
    k_gru_scan<<<NBLK, SCAN_THREADS, SCAN_SMEM>>>(p_gi, Wh_enc, bh_enc, p_h);

    // 3) phi_enc = relu(h_all @ Wphi_enc[:, :H].T + b)
    {
        dim3 grid(BT / 128, D / 128);
        k_gemm_ht<<<grid, 256>>>(p_h, Wphi_enc, H + Z, bphi_enc, p_phi, D, H, 1);
    }
    // 4) z heads (fused N=128 GEMM)
    {
        dim3 grid(BT / 128, 1);
        k_gemm<<<grid, 256>>>(p_phi, D, p_WhZ, D, p_bhZ, p_head, 128, D, 0, 0);
    }
    // 5) flow + z outputs + kld_z partials
    k_flow_enc<<<BT / 4, 256>>>(p_head, eps_enc, w_flow, b_flow, u_flow, out, p_z, p_pz);

    // 6) gi_dec = z_all @ Wi_dec.T + bi_dec -> transposed
    {
        dim3 grid(BT / 128, G / 128);
        k_gemm<<<grid, 256>>>(p_z, Z, Wi_dec, Z, bi_dec, p_gi, G, Z, 0, 1);
    }
    // 7) decoder GRU scan (h slab 0 still zero)
    k_gru_scan<<<NBLK, SCAN_THREADS, SCAN_SMEM>>>(p_gi, Wh_dec, bh_dec, p_h);

    // 8) phi_dec
    {
        dim3 grid(BT / 128, D / 128);
        k_gemm_ht<<<grid, 256>>>(p_h, Wphi_dec, H, bphi_dec, p_phi, D, H, 1);
    }
    // 9) x heads (fused)
    {
        dim3 grid(BT / 128, 1);
        k_gemm<<<grid, 256>>>(p_phi, D, p_WhX, D, p_bhX, p_head, 128, D, 0, 0);
    }
    // 10) decoder outputs + nll/kld_x partials
    k_dec_out<<<S / 256, 256>>>(p_head, eps_dec, x, out, p_pn, p_px);

    // 11) final reduction
    k_reduce_final<<<1, 256>>>(p_pz, p_pn, p_px, out);
}